// round 14
// baseline (speedup 1.0000x reference)
#include <cuda_runtime.h>
#include <cuda_fp16.h>
#include <math.h>
#include <stdint.h>

// Problem constants
#define BATCH 4
#define SEQ 2048
#define DMODEL 1024
#define NHEAD 16
#define ROWS (BATCH * SEQ)   // 8192

// ---------------------------------------------------------------------------
// Scratch (device globals; no allocation allowed)
// ---------------------------------------------------------------------------
__device__ __half g_x2h[ROWS * DMODEL];
__device__ __half g_qh[ROWS * DMODEL];
__device__ __half g_kh[ROWS * DMODEL];
__device__ __half g_vh[ROWS * DMODEL];
__device__ __half g_attnh[ROWS * DMODEL];
__device__ __half g_ffh[ROWS * DMODEL];
__device__ float g_xmid[ROWS * DMODEL];
__device__ __half g_wth[6 * DMODEL * DMODEL];   // transposed fp16 weights [N][K]

// ---------------------------------------------------------------------------
// helpers
// ---------------------------------------------------------------------------
__device__ __forceinline__ void mma_f16(
    float& c0, float& c1, float& c2, float& c3,
    unsigned a0, unsigned a1, unsigned a2, unsigned a3,
    unsigned b0, unsigned b1) {
  asm("mma.sync.aligned.m16n8k16.row.col.f32.f16.f16.f32 "
      "{%0,%1,%2,%3}, {%4,%5,%6,%7}, {%8,%9}, {%0,%1,%2,%3};"
      : "+f"(c0), "+f"(c1), "+f"(c2), "+f"(c3)
      : "r"(a0), "r"(a1), "r"(a2), "r"(a3), "r"(b0), "r"(b1));
}

__device__ __forceinline__ void ldsm_x4(uint32_t& r0, uint32_t& r1,
                                        uint32_t& r2, uint32_t& r3, uint32_t a) {
  asm volatile("ldmatrix.sync.aligned.m8n8.x4.shared.b16 {%0,%1,%2,%3}, [%4];"
               : "=r"(r0), "=r"(r1), "=r"(r2), "=r"(r3) : "r"(a));
}
__device__ __forceinline__ void ldsm_x4_t(uint32_t& r0, uint32_t& r1,
                                          uint32_t& r2, uint32_t& r3, uint32_t a) {
  asm volatile("ldmatrix.sync.aligned.m8n8.x4.trans.shared.b16 {%0,%1,%2,%3}, [%4];"
               : "=r"(r0), "=r"(r1), "=r"(r2), "=r"(r3) : "r"(a));
}

__device__ __forceinline__ void cp_async16(void* smem_dst, const void* gmem_src) {
  unsigned s = (unsigned)__cvta_generic_to_shared(smem_dst);
  asm volatile("cp.async.ca.shared.global [%0], [%1], 16;\n" ::"r"(s),
               "l"(gmem_src));
}
__device__ __forceinline__ void cp_commit() {
  asm volatile("cp.async.commit_group;\n" ::);
}
template <int N>
__device__ __forceinline__ void cp_wait() {
  asm volatile("cp.async.wait_group %0;\n" ::"n"(N));
}

__device__ __forceinline__ float gelu_f(float v) {
  float t = tanhf(0.7978845608028654f * (v + 0.044715f * v * v * v));
  return 0.5f * v * (1.0f + t);
}

__device__ __forceinline__ unsigned h2u(__half2 h) { return *(unsigned*)&h; }

// ---------------------------------------------------------------------------
// LayerNorm: f32 in -> fp16 out
// ---------------------------------------------------------------------------
__global__ void __launch_bounds__(256) layernorm_kernel(
    const float* __restrict__ x, const float* __restrict__ alpha,
    const float* __restrict__ beta, __half* __restrict__ y) {
  __shared__ float red[8];
  __shared__ float bcast;
  const int row = blockIdx.x;
  const int tid = threadIdx.x;
  const float* xp = x + (size_t)row * DMODEL;

  float4 v = *(const float4*)(xp + tid * 4);
  float s = v.x + v.y + v.z + v.w;
#pragma unroll
  for (int o = 16; o; o >>= 1) s += __shfl_xor_sync(0xffffffffu, s, o);
  if ((tid & 31) == 0) red[tid >> 5] = s;
  __syncthreads();
  if (tid == 0) {
    float t = 0.f;
#pragma unroll
    for (int i = 0; i < 8; i++) t += red[i];
    bcast = t;
  }
  __syncthreads();
  const float mean = bcast * (1.0f / (float)DMODEL);
  __syncthreads();

  const float dx = v.x - mean, dy = v.y - mean, dz = v.z - mean, dw = v.w - mean;
  float sq = dx * dx + dy * dy + dz * dz + dw * dw;
#pragma unroll
  for (int o = 16; o; o >>= 1) sq += __shfl_xor_sync(0xffffffffu, sq, o);
  if ((tid & 31) == 0) red[tid >> 5] = sq;
  __syncthreads();
  if (tid == 0) {
    float t = 0.f;
#pragma unroll
    for (int i = 0; i < 8; i++) t += red[i];
    bcast = t;
  }
  __syncthreads();
  const float var = bcast * (1.0f / (float)(DMODEL - 1));
  const float sc = 1.0f / (sqrtf(var) + 1e-6f);

  const float4 a4 = *(const float4*)(alpha + tid * 4);
  const float4 b4 = *(const float4*)(beta + tid * 4);
  __half2 h01 = __floats2half2_rn(a4.x * dx * sc + b4.x, a4.y * dy * sc + b4.y);
  __half2 h23 = __floats2half2_rn(a4.z * dz * sc + b4.z, a4.w * dw * sc + b4.w);
  uint2 u = {h2u(h01), h2u(h23)};
  *(uint2*)(y + (size_t)row * DMODEL + tid * 4) = u;
}

// ---------------------------------------------------------------------------
// Weight transpose prepass: Wt[n][k] = (half)W[k][n]
// ---------------------------------------------------------------------------
__global__ void __launch_bounds__(256) transpose6_kernel(
    const float* __restrict__ Wq, const float* __restrict__ Wk,
    const float* __restrict__ Wv, const float* __restrict__ Wo,
    const float* __restrict__ W1, const float* __restrict__ W2,
    __half* __restrict__ wt) {
  const float* src;
  switch (blockIdx.z) {
    case 0: src = Wq; break;
    case 1: src = Wk; break;
    case 2: src = Wv; break;
    case 3: src = Wo; break;
    case 4: src = W1; break;
    default: src = W2; break;
  }
  __half* dst = wt + (size_t)blockIdx.z * DMODEL * DMODEL;
  __shared__ float tl[32][33];
  const int tx = threadIdx.x, ty = threadIdx.y;
  const int x = blockIdx.x * 32 + tx;
  const int y = blockIdx.y * 32 + ty;
#pragma unroll
  for (int i = 0; i < 32; i += 8)
    tl[ty + i][tx] = src[(size_t)(y + i) * DMODEL + x];
  __syncthreads();
  const int x2 = blockIdx.y * 32 + tx;
  const int y2 = blockIdx.x * 32 + ty;
#pragma unroll
  for (int i = 0; i < 32; i += 8)
    dst[(size_t)(y2 + i) * DMODEL + x2] = __float2half_rn(tl[tx][ty + i]);
}

// ---------------------------------------------------------------------------
// fp16 TC GEMM: BM=128 BN=128 BK=64, 3-stage cp.async, ldmatrix fragments.
// 256 thr = 8 warps (2m x 4n), warp tile 64x32 via m16n8k16.
// smem row = 64 halves + 8 pad = 72 halves (144B): ldmatrix phases
// conflict-free (4r mod 32 distinct per 8-row phase).
// ---------------------------------------------------------------------------
#define GROWB 144                              // bytes per padded row
#define GA_BYTES (128 * GROWB)                 // 18432
#define GSTAGE_BYTES (2 * GA_BYTES)            // 36864
#define GNSTAGE 3
#define HGEMM_SMEM (GSTAGE_BYTES * GNSTAGE)    // 110592

template <int EPI, typename OutT>  // 0=bias, 1=bias+gelu, 2=bias+residual(f32)
__device__ __forceinline__ void hgemm_body(
    const __half* __restrict__ A, const __half* __restrict__ Bt,
    const float* __restrict__ bias, const float* __restrict__ res,
    OutT* __restrict__ C) {
  extern __shared__ char smc[];
  const uint32_t sb = (uint32_t)__cvta_generic_to_shared(smc);
  const int tid = threadIdx.x;
  const int cRow = blockIdx.y, cCol = blockIdx.x;
  const int lane = tid & 31, warp = tid >> 5;
  const int lr = lane >> 2, lc = lane & 3;
  const int m0 = (warp & 1) * 64;
  const int n0 = (warp >> 1) * 32;

  // cp.async mapping: thread covers row (tid>>1), chunks c0..c0+3 (16B each)
  const int grow = tid >> 1;
  const int gc0 = (tid & 1) * 4;

  const __half* Ap = A + (size_t)(cRow * 128 + grow) * DMODEL;
  const __half* Bp = Bt + (size_t)(cCol * 128 + grow) * DMODEL;

  float acc[4][4][4];
#pragma unroll
  for (int i = 0; i < 4; i++)
#pragma unroll
    for (int j = 0; j < 4; j++)
#pragma unroll
      for (int q = 0; q < 4; q++) acc[i][j][q] = 0.f;

  const int NT = DMODEL / 64;  // 16

  auto issue = [&](int s, int t) {
    char* base = smc + s * GSTAGE_BYTES;
    const int k0 = t * 64;
#pragma unroll
    for (int c = 0; c < 4; c++) {
      const int cc = gc0 + c;
      cp_async16(base + grow * GROWB + cc * 16, Ap + k0 + cc * 8);
      cp_async16(base + GA_BYTES + grow * GROWB + cc * 16, Bp + k0 + cc * 8);
    }
  };

  issue(0, 0); cp_commit();
  issue(1, 1); cp_commit();

  for (int t = 0; t < NT; t++) {
    cp_wait<1>();
    __syncthreads();

    const uint32_t sA = sb + (t % 3) * GSTAGE_BYTES;
    const uint32_t sB = sA + GA_BYTES;

#pragma unroll
    for (int ks = 0; ks < 4; ks++) {
      uint32_t af[4][4], bf[4][2];
#pragma unroll
      for (int mt = 0; mt < 4; mt++) {
        const uint32_t a = sA + (m0 + mt * 16 + (lane & 15)) * GROWB +
                           ks * 32 + (lane >> 4) * 16;
        ldsm_x4(af[mt][0], af[mt][1], af[mt][2], af[mt][3], a);
      }
#pragma unroll
      for (int ntp = 0; ntp < 2; ntp++) {
        const uint32_t a = sB +
            (n0 + ntp * 16 + (lane & 7) + ((lane >> 4) & 1) * 8) * GROWB +
            ks * 32 + ((lane >> 3) & 1) * 16;
        uint32_t t0, t1, t2, t3;
        ldsm_x4(t0, t1, t2, t3, a);
        bf[2 * ntp][0] = t0;     bf[2 * ntp][1] = t1;
        bf[2 * ntp + 1][0] = t2; bf[2 * ntp + 1][1] = t3;
      }
#pragma unroll
      for (int mt = 0; mt < 4; mt++)
#pragma unroll
        for (int nt = 0; nt < 4; nt++)
          mma_f16(acc[mt][nt][0], acc[mt][nt][1], acc[mt][nt][2], acc[mt][nt][3],
                  af[mt][0], af[mt][1], af[mt][2], af[mt][3],
                  bf[nt][0], bf[nt][1]);
    }

    if (t + 2 < NT) issue((t + 2) % 3, t + 2);
    cp_commit();
  }

  // epilogue
#pragma unroll
  for (int mt = 0; mt < 4; mt++) {
    const int r0 = cRow * 128 + m0 + mt * 16 + lr;
#pragma unroll
    for (int nt = 0; nt < 4; nt++) {
      const int col = cCol * 128 + n0 + nt * 8 + 2 * lc;
      const float bx = bias[col], by = bias[col + 1];
      float v0 = acc[mt][nt][0] + bx, v1 = acc[mt][nt][1] + by;
      float v2 = acc[mt][nt][2] + bx, v3 = acc[mt][nt][3] + by;
      if (EPI == 1) { v0 = gelu_f(v0); v1 = gelu_f(v1); v2 = gelu_f(v2); v3 = gelu_f(v3); }
      if (EPI == 2) {
        const float2 r4a = *(const float2*)(res + (size_t)r0 * DMODEL + col);
        const float2 r4b = *(const float2*)(res + (size_t)(r0 + 8) * DMODEL + col);
        v0 += r4a.x; v1 += r4a.y; v2 += r4b.x; v3 += r4b.y;
      }
      if (sizeof(OutT) == 2) {
        __half2 h0 = __floats2half2_rn(v0, v1);
        __half2 h1 = __floats2half2_rn(v2, v3);
        *(__half2*)((__half*)C + (size_t)r0 * DMODEL + col) = h0;
        *(__half2*)((__half*)C + (size_t)(r0 + 8) * DMODEL + col) = h1;
      } else {
        float2 o0 = {v0, v1}, o1 = {v2, v3};
        *(float2*)((float*)C + (size_t)r0 * DMODEL + col) = o0;
        *(float2*)((float*)C + (size_t)(r0 + 8) * DMODEL + col) = o1;
      }
    }
  }
}

template <int EPI, typename OutT>
__global__ void __launch_bounds__(256) hgemm_kernel(
    const __half* __restrict__ A, const __half* __restrict__ Bt,
    const float* __restrict__ bias, const float* __restrict__ res,
    OutT* __restrict__ C) {
  hgemm_body<EPI, OutT>(A, Bt, bias, res, C);
}

__global__ void __launch_bounds__(256) hqkv_kernel(
    const __half* __restrict__ A, const __half* __restrict__ wt,
    const float* __restrict__ bq, __half* __restrict__ q,
    const float* __restrict__ bk, __half* __restrict__ k,
    const float* __restrict__ bv, __half* __restrict__ v) {
  const __half* Bt;
  const float* bias;
  __half* C;
  if (blockIdx.z == 0)      { Bt = wt;                               bias = bq; C = q; }
  else if (blockIdx.z == 1) { Bt = wt + (size_t)DMODEL * DMODEL;     bias = bk; C = k; }
  else                      { Bt = wt + (size_t)2 * DMODEL * DMODEL; bias = bv; C = v; }
  hgemm_body<0, __half>(A, Bt, bias, nullptr, C);
}

// ---------------------------------------------------------------------------
// Flash attention (causal), fp16 mma, register-resident softmax (R12, proven)
// ---------------------------------------------------------------------------
#define AT_STR 72
#define AT_QOFF 0
#define AT_KOFF 9216
#define AT_VOFF 27648
#define AT_STOFF 46080
#define ATTN_SMEM_H (AT_STOFF + 1024 + 128)   // 47232

__global__ void __launch_bounds__(256) flash_attn_h16_kernel(
    const __half* __restrict__ Q, const __half* __restrict__ K,
    const __half* __restrict__ V, __half* __restrict__ O) {
  extern __shared__ char smc[];
  const uint32_t sb = (uint32_t)__cvta_generic_to_shared(smc);
  __half* Qf = (__half*)(smc + AT_QOFF);
  __half* Kf = (__half*)(smc + AT_KOFF);
  __half* Vf = (__half*)(smc + AT_VOFF);
  float* stat_max = (float*)(smc + AT_STOFF);
  float* stat_sum = (float*)(smc + AT_STOFF + 512);
  float* ebuf = (float*)smc;

  const int qt = blockIdx.x, h = blockIdx.y, b = blockIdx.z;
  const int tid = threadIdx.x, lane = tid & 31, warp = tid >> 5;
  const int lr = lane >> 2, lc = lane & 3;
  const int pair = warp >> 1, khalf = warp & 1;
  const int mq = pair * 16, nq = khalf * 32;
  const int q0 = qt * 64;

#pragma unroll
  for (int i = 0; i < 2; i++) {
    const int idx = tid + i * 256;
    const int r = idx >> 3, c = idx & 7;
    cp_async16(Qf + r * AT_STR + c * 8,
               Q + (((size_t)((b * SEQ + q0 + r) * NHEAD + h)) << 6) + c * 8);
  }
#pragma unroll
  for (int i = 0; i < 2; i++) {
    const int idx = tid + i * 256;
    const int r = idx >> 3, c = idx & 7;
    const size_t g = (((size_t)((b * SEQ + r) * NHEAD + h)) << 6) + c * 8;
    cp_async16(Kf + r * AT_STR + c * 8, K + g);
    cp_async16(Vf + r * AT_STR + c * 8, V + g);
  }
  cp_commit();
  cp_wait<0>();
  __syncthreads();

  uint32_t qa[4][4];
  {
    const int qrow = mq + (lane & 15);
#pragma unroll
    for (int ks = 0; ks < 4; ks++) {
      const uint32_t a = sb + AT_QOFF +
                         (qrow * AT_STR + ks * 16 + (lane >> 4) * 8) * 2;
      ldsm_x4(qa[ks][0], qa[ks][1], qa[ks][2], qa[ks][3], a);
    }
  }

  float oacc[8][4];
#pragma unroll
  for (int nt = 0; nt < 8; nt++)
#pragma unroll
    for (int q = 0; q < 4; q++) oacc[nt][q] = 0.f;

  const int r0 = mq + lr, r1 = mq + 8 + lr;
  float mrow0 = -1e30f, mrow1 = -1e30f, lrow0 = 0.f, lrow1 = 0.f;

  for (int kt = 0; kt <= qt; kt++) {
    const int buf = kt & 1;
    __syncthreads();
    if (kt < qt) {
      const int nb = buf ^ 1;
#pragma unroll
      for (int i = 0; i < 2; i++) {
        const int idx = tid + i * 256;
        const int r = idx >> 3, c = idx & 7;
        const size_t g =
            (((size_t)((b * SEQ + (kt + 1) * 64 + r) * NHEAD + h)) << 6) + c * 8;
        cp_async16(Kf + nb * 4608 + r * AT_STR + c * 8, K + g);
        cp_async16(Vf + nb * 4608 + r * AT_STR + c * 8, V + g);
      }
      cp_commit();
      cp_wait<1>();
    } else {
      cp_wait<0>();
    }
    __syncthreads();

    const uint32_t kbase = sb + AT_KOFF + buf * 9216;
    const uint32_t vbase = sb + AT_VOFF + buf * 9216;

    float sacc[4][4];
#pragma unroll
    for (int nt = 0; nt < 4; nt++)
#pragma unroll
      for (int q = 0; q < 4; q++) sacc[nt][q] = 0.f;
#pragma unroll
    for (int ks = 0; ks < 4; ks++) {
      uint32_t kb[4][2];
#pragma unroll
      for (int hh = 0; hh < 2; hh++) {
        const uint32_t a = kbase +
            ((nq + hh * 16 + (lane & 15)) * AT_STR + ks * 16 + (lane >> 4) * 8) * 2;
        uint32_t t0, t1, t2, t3;
        ldsm_x4(t0, t1, t2, t3, a);
        kb[2 * hh][0] = t0; kb[2 * hh + 1][0] = t1;
        kb[2 * hh][1] = t2; kb[2 * hh + 1][1] = t3;
      }
#pragma unroll
      for (int nt = 0; nt < 4; nt++)
        mma_f16(sacc[nt][0], sacc[nt][1], sacc[nt][2], sacc[nt][3],
                qa[ks][0], qa[ks][1], qa[ks][2], qa[ks][3],
                kb[nt][0], kb[nt][1]);
    }

#pragma unroll
    for (int nt = 0; nt < 4; nt++)
#pragma unroll
      for (int q = 0; q < 4; q++) sacc[nt][q] *= 0.125f;
    if (kt == qt) {
#pragma unroll
      for (int nt = 0; nt < 4; nt++) {
        const int cl = nq + nt * 8 + 2 * lc;
        if (cl > r0) sacc[nt][0] = -1e9f;
        if (cl + 1 > r0) sacc[nt][1] = -1e9f;
        if (cl > r1) sacc[nt][2] = -1e9f;
        if (cl + 1 > r1) sacc[nt][3] = -1e9f;
      }
    }

    float tm0 = sacc[0][0], tm1 = sacc[0][2];
#pragma unroll
    for (int nt = 0; nt < 4; nt++) {
      tm0 = fmaxf(tm0, fmaxf(sacc[nt][0], sacc[nt][1]));
      tm1 = fmaxf(tm1, fmaxf(sacc[nt][2], sacc[nt][3]));
    }
    tm0 = fmaxf(tm0, __shfl_xor_sync(0xffffffffu, tm0, 1));
    tm0 = fmaxf(tm0, __shfl_xor_sync(0xffffffffu, tm0, 2));
    tm1 = fmaxf(tm1, __shfl_xor_sync(0xffffffffu, tm1, 1));
    tm1 = fmaxf(tm1, __shfl_xor_sync(0xffffffffu, tm1, 2));
    if (lc == 0) {
      stat_max[r0 * 2 + khalf] = tm0;
      stat_max[r1 * 2 + khalf] = tm1;
    }
    __syncthreads();
    const float mt0 = fmaxf(stat_max[r0 * 2], stat_max[r0 * 2 + 1]);
    const float mt1 = fmaxf(stat_max[r1 * 2], stat_max[r1 * 2 + 1]);
    const float mnew0 = fmaxf(mrow0, mt0), mnew1 = fmaxf(mrow1, mt1);
    const float corr0 = __expf(mrow0 - mnew0), corr1 = __expf(mrow1 - mnew1);

    float ev[4][4];
    float ps0 = 0.f, ps1 = 0.f;
#pragma unroll
    for (int nt = 0; nt < 4; nt++) {
      ev[nt][0] = __expf(sacc[nt][0] - mnew0);
      ev[nt][1] = __expf(sacc[nt][1] - mnew0);
      ev[nt][2] = __expf(sacc[nt][2] - mnew1);
      ev[nt][3] = __expf(sacc[nt][3] - mnew1);
      ps0 += ev[nt][0] + ev[nt][1];
      ps1 += ev[nt][2] + ev[nt][3];
    }
    ps0 += __shfl_xor_sync(0xffffffffu, ps0, 1);
    ps0 += __shfl_xor_sync(0xffffffffu, ps0, 2);
    ps1 += __shfl_xor_sync(0xffffffffu, ps1, 1);
    ps1 += __shfl_xor_sync(0xffffffffu, ps1, 2);
    if (lc == 0) {
      stat_sum[r0 * 2 + khalf] = ps0;
      stat_sum[r1 * 2 + khalf] = ps1;
    }
    uint32_t pa[2][4];
#pragma unroll
    for (int ks2 = 0; ks2 < 2; ks2++) {
      pa[ks2][0] = h2u(__floats2half2_rn(ev[2 * ks2][0], ev[2 * ks2][1]));
      pa[ks2][1] = h2u(__floats2half2_rn(ev[2 * ks2][2], ev[2 * ks2][3]));
      pa[ks2][2] = h2u(__floats2half2_rn(ev[2 * ks2 + 1][0], ev[2 * ks2 + 1][1]));
      pa[ks2][3] = h2u(__floats2half2_rn(ev[2 * ks2 + 1][2], ev[2 * ks2 + 1][3]));
    }
    __syncthreads();
    lrow0 = lrow0 * corr0 + (stat_sum[r0 * 2] + stat_sum[r0 * 2 + 1]);
    lrow1 = lrow1 * corr1 + (stat_sum[r1 * 2] + stat_sum[r1 * 2 + 1]);
    mrow0 = mnew0; mrow1 = mnew1;

#pragma unroll
    for (int nt = 0; nt < 8; nt++) {
      oacc[nt][0] *= corr0; oacc[nt][1] *= corr0;
      oacc[nt][2] *= corr1; oacc[nt][3] *= corr1;
    }
#pragma unroll
    for (int ks2 = 0; ks2 < 2; ks2++) {
      uint32_t vb[8][2];
#pragma unroll
      for (int hh = 0; hh < 4; hh++) {
        const uint32_t a = vbase +
            ((nq + ks2 * 16 + (lane & 15)) * AT_STR + hh * 16 + (lane >> 4) * 8) * 2;
        uint32_t t0, t1, t2, t3;
        ldsm_x4_t(t0, t1, t2, t3, a);
        vb[2 * hh][0] = t0;     vb[2 * hh][1] = t1;
        vb[2 * hh + 1][0] = t2; vb[2 * hh + 1][1] = t3;
      }
#pragma unroll
      for (int nt = 0; nt < 8; nt++)
        mma_f16(oacc[nt][0], oacc[nt][1], oacc[nt][2], oacc[nt][3],
                pa[ks2][0], pa[ks2][1], pa[ks2][2], pa[ks2][3],
                vb[nt][0], vb[nt][1]);
    }
  }

  __syncthreads();
  if (khalf == 1) {
#pragma unroll
    for (int nt = 0; nt < 8; nt++) {
      const int col = nt * 8 + 2 * lc;
      *(float2*)&ebuf[(mq + lr) * 68 + col] =
          make_float2(oacc[nt][0], oacc[nt][1]);
      *(float2*)&ebuf[(mq + 8 + lr) * 68 + col] =
          make_float2(oacc[nt][2], oacc[nt][3]);
    }
  }
  __syncthreads();
  if (khalf == 0) {
    const float inv0 = 1.0f / lrow0, inv1 = 1.0f / lrow1;
#pragma unroll
    for (int nt = 0; nt < 8; nt++) {
      const int col = nt * 8 + 2 * lc;
      const float2 p0 = *(const float2*)&ebuf[(mq + lr) * 68 + col];
      const float2 p1 = *(const float2*)&ebuf[(mq + 8 + lr) * 68 + col];
      __half* o0 = O + (((size_t)((b * SEQ + q0 + mq + lr) * NHEAD + h)) << 6) + col;
      __half* o1 =
          O + (((size_t)((b * SEQ + q0 + mq + 8 + lr) * NHEAD + h)) << 6) + col;
      *(__half2*)o0 = __floats2half2_rn((oacc[nt][0] + p0.x) * inv0,
                                        (oacc[nt][1] + p0.y) * inv0);
      *(__half2*)o1 = __floats2half2_rn((oacc[nt][2] + p1.x) * inv1,
                                        (oacc[nt][3] + p1.y) * inv1);
    }
  }
}

// ---------------------------------------------------------------------------
// Launch
// ---------------------------------------------------------------------------
extern "C" void kernel_launch(void* const* d_in, const int* in_sizes, int n_in,
                              void* d_out, int out_size) {
  (void)in_sizes; (void)n_in; (void)out_size;
  const float* x      = (const float*)d_in[0];
  const float* Wq     = (const float*)d_in[2];
  const float* bq     = (const float*)d_in[3];
  const float* Wk     = (const float*)d_in[4];
  const float* bk     = (const float*)d_in[5];
  const float* Wv     = (const float*)d_in[6];
  const float* bv     = (const float*)d_in[7];
  const float* Wo     = (const float*)d_in[8];
  const float* bo     = (const float*)d_in[9];
  const float* W1     = (const float*)d_in[10];
  const float* b1     = (const float*)d_in[11];
  const float* W2     = (const float*)d_in[12];
  const float* b2     = (const float*)d_in[13];
  const float* alpha1 = (const float*)d_in[14];
  const float* bias1  = (const float*)d_in[15];
  const float* alpha2 = (const float*)d_in[16];
  const float* bias2  = (const float*)d_in[17];
  float* out = (float*)d_out;

  __half *x2h, *qh, *kh, *vh, *attnh, *ffh, *wth;
  float* xmid;
  cudaGetSymbolAddress((void**)&x2h, g_x2h);
  cudaGetSymbolAddress((void**)&qh, g_qh);
  cudaGetSymbolAddress((void**)&kh, g_kh);
  cudaGetSymbolAddress((void**)&vh, g_vh);
  cudaGetSymbolAddress((void**)&attnh, g_attnh);
  cudaGetSymbolAddress((void**)&ffh, g_ffh);
  cudaGetSymbolAddress((void**)&xmid, g_xmid);
  cudaGetSymbolAddress((void**)&wth, g_wth);

  cudaFuncSetAttribute(flash_attn_h16_kernel,
                       cudaFuncAttributeMaxDynamicSharedMemorySize, ATTN_SMEM_H);
  cudaFuncSetAttribute(hgemm_kernel<1, __half>,
                       cudaFuncAttributeMaxDynamicSharedMemorySize, HGEMM_SMEM);
  cudaFuncSetAttribute(hgemm_kernel<2, float>,
                       cudaFuncAttributeMaxDynamicSharedMemorySize, HGEMM_SMEM);
  cudaFuncSetAttribute(hqkv_kernel,
                       cudaFuncAttributeMaxDynamicSharedMemorySize, HGEMM_SMEM);

  const dim3 gemm_grid(DMODEL / 128, ROWS / 128);
  const dim3 qkv_grid(DMODEL / 128, ROWS / 128, 3);

  transpose6_kernel<<<dim3(32, 32, 6), dim3(32, 8)>>>(Wq, Wk, Wv, Wo, W1, W2, wth);
  layernorm_kernel<<<ROWS, 256>>>(x, alpha1, bias1, x2h);
  hqkv_kernel<<<qkv_grid, 256, HGEMM_SMEM>>>(x2h, wth, bq, qh, bk, kh, bv, vh);
  flash_attn_h16_kernel<<<dim3(SEQ / 64, NHEAD, BATCH), 256, ATTN_SMEM_H>>>(
      qh, kh, vh, attnh);
  hgemm_kernel<2, float><<<gemm_grid, 256, HGEMM_SMEM>>>(
      attnh, wth + (size_t)3 * DMODEL * DMODEL, bo, x, xmid);
  layernorm_kernel<<<ROWS, 256>>>(xmid, alpha2, bias2, x2h);
  hgemm_kernel<1, __half><<<gemm_grid, 256, HGEMM_SMEM>>>(
      x2h, wth + (size_t)4 * DMODEL * DMODEL, b1, nullptr, ffh);
  hgemm_kernel<2, float><<<gemm_grid, 256, HGEMM_SMEM>>>(
      ffh, wth + (size_t)5 * DMODEL * DMODEL, b2, xmid, out);
}

// round 15
// speedup vs baseline: 1.1476x; 1.1476x over previous
#include <cuda_runtime.h>
#include <cuda_fp16.h>
#include <math.h>
#include <stdint.h>

// Problem constants
#define BATCH 4
#define SEQ 2048
#define DMODEL 1024
#define NHEAD 16
#define ROWS (BATCH * SEQ)   // 8192

// ---------------------------------------------------------------------------
// Scratch (device globals; no allocation allowed)
// ---------------------------------------------------------------------------
__device__ __half g_x2h[ROWS * DMODEL];
__device__ __half g_qh[ROWS * DMODEL];
__device__ __half g_kh[ROWS * DMODEL];
__device__ __half g_vh[ROWS * DMODEL];
__device__ __half g_attnh[ROWS * DMODEL];
__device__ __half g_ffh[ROWS * DMODEL];
__device__ float g_xmid[ROWS * DMODEL];
__device__ __half g_wth[6 * DMODEL * DMODEL];   // transposed fp16 weights [N][K]

// ---------------------------------------------------------------------------
// helpers
// ---------------------------------------------------------------------------
__device__ __forceinline__ void mma_f16(
    float& c0, float& c1, float& c2, float& c3,
    unsigned a0, unsigned a1, unsigned a2, unsigned a3,
    unsigned b0, unsigned b1) {
  asm("mma.sync.aligned.m16n8k16.row.col.f32.f16.f16.f32 "
      "{%0,%1,%2,%3}, {%4,%5,%6,%7}, {%8,%9}, {%0,%1,%2,%3};"
      : "+f"(c0), "+f"(c1), "+f"(c2), "+f"(c3)
      : "r"(a0), "r"(a1), "r"(a2), "r"(a3), "r"(b0), "r"(b1));
}

__device__ __forceinline__ void ldsm_x4(uint32_t& r0, uint32_t& r1,
                                        uint32_t& r2, uint32_t& r3, uint32_t a) {
  asm volatile("ldmatrix.sync.aligned.m8n8.x4.shared.b16 {%0,%1,%2,%3}, [%4];"
               : "=r"(r0), "=r"(r1), "=r"(r2), "=r"(r3) : "r"(a));
}
__device__ __forceinline__ void ldsm_x4_t(uint32_t& r0, uint32_t& r1,
                                          uint32_t& r2, uint32_t& r3, uint32_t a) {
  asm volatile("ldmatrix.sync.aligned.m8n8.x4.trans.shared.b16 {%0,%1,%2,%3}, [%4];"
               : "=r"(r0), "=r"(r1), "=r"(r2), "=r"(r3) : "r"(a));
}

__device__ __forceinline__ void cp_async16(void* smem_dst, const void* gmem_src) {
  unsigned s = (unsigned)__cvta_generic_to_shared(smem_dst);
  asm volatile("cp.async.ca.shared.global [%0], [%1], 16;\n" ::"r"(s),
               "l"(gmem_src));
}
__device__ __forceinline__ void cp_commit() {
  asm volatile("cp.async.commit_group;\n" ::);
}
template <int N>
__device__ __forceinline__ void cp_wait() {
  asm volatile("cp.async.wait_group %0;\n" ::"n"(N));
}

__device__ __forceinline__ float gelu_f(float v) {
  float t = tanhf(0.7978845608028654f * (v + 0.044715f * v * v * v));
  return 0.5f * v * (1.0f + t);
}

__device__ __forceinline__ unsigned h2u(__half2 h) { return *(unsigned*)&h; }

// ---------------------------------------------------------------------------
// LayerNorm: f32 in -> fp16 out
// ---------------------------------------------------------------------------
__global__ void __launch_bounds__(256) layernorm_kernel(
    const float* __restrict__ x, const float* __restrict__ alpha,
    const float* __restrict__ beta, __half* __restrict__ y) {
  __shared__ float red[8];
  __shared__ float bcast;
  const int row = blockIdx.x;
  const int tid = threadIdx.x;
  const float* xp = x + (size_t)row * DMODEL;

  float4 v = *(const float4*)(xp + tid * 4);
  float s = v.x + v.y + v.z + v.w;
#pragma unroll
  for (int o = 16; o; o >>= 1) s += __shfl_xor_sync(0xffffffffu, s, o);
  if ((tid & 31) == 0) red[tid >> 5] = s;
  __syncthreads();
  if (tid == 0) {
    float t = 0.f;
#pragma unroll
    for (int i = 0; i < 8; i++) t += red[i];
    bcast = t;
  }
  __syncthreads();
  const float mean = bcast * (1.0f / (float)DMODEL);
  __syncthreads();

  const float dx = v.x - mean, dy = v.y - mean, dz = v.z - mean, dw = v.w - mean;
  float sq = dx * dx + dy * dy + dz * dz + dw * dw;
#pragma unroll
  for (int o = 16; o; o >>= 1) sq += __shfl_xor_sync(0xffffffffu, sq, o);
  if ((tid & 31) == 0) red[tid >> 5] = sq;
  __syncthreads();
  if (tid == 0) {
    float t = 0.f;
#pragma unroll
    for (int i = 0; i < 8; i++) t += red[i];
    bcast = t;
  }
  __syncthreads();
  const float var = bcast * (1.0f / (float)(DMODEL - 1));
  const float sc = 1.0f / (sqrtf(var) + 1e-6f);

  const float4 a4 = *(const float4*)(alpha + tid * 4);
  const float4 b4 = *(const float4*)(beta + tid * 4);
  __half2 h01 = __floats2half2_rn(a4.x * dx * sc + b4.x, a4.y * dy * sc + b4.y);
  __half2 h23 = __floats2half2_rn(a4.z * dz * sc + b4.z, a4.w * dw * sc + b4.w);
  uint2 u = {h2u(h01), h2u(h23)};
  *(uint2*)(y + (size_t)row * DMODEL + tid * 4) = u;
}

// ---------------------------------------------------------------------------
// Weight transpose prepass: Wt[n][k] = (half)W[k][n]
// ---------------------------------------------------------------------------
__global__ void __launch_bounds__(256) transpose6_kernel(
    const float* __restrict__ Wq, const float* __restrict__ Wk,
    const float* __restrict__ Wv, const float* __restrict__ Wo,
    const float* __restrict__ W1, const float* __restrict__ W2,
    __half* __restrict__ wt) {
  const float* src;
  switch (blockIdx.z) {
    case 0: src = Wq; break;
    case 1: src = Wk; break;
    case 2: src = Wv; break;
    case 3: src = Wo; break;
    case 4: src = W1; break;
    default: src = W2; break;
  }
  __half* dst = wt + (size_t)blockIdx.z * DMODEL * DMODEL;
  __shared__ float tl[32][33];
  const int tx = threadIdx.x, ty = threadIdx.y;
  const int x = blockIdx.x * 32 + tx;
  const int y = blockIdx.y * 32 + ty;
#pragma unroll
  for (int i = 0; i < 32; i += 8)
    tl[ty + i][tx] = src[(size_t)(y + i) * DMODEL + x];
  __syncthreads();
  const int x2 = blockIdx.y * 32 + tx;
  const int y2 = blockIdx.x * 32 + ty;
#pragma unroll
  for (int i = 0; i < 32; i += 8)
    dst[(size_t)(y2 + i) * DMODEL + x2] = __float2half_rn(tl[tx][ty + i]);
}

// ---------------------------------------------------------------------------
// fp16 TC GEMM — exact R12 proven version (BK=32, 4-stage, scalar frag LDS)
// ---------------------------------------------------------------------------
#define HBK 32
#define HROWB 80
#define HA_BYTES (128 * HROWB)
#define HSTAGE_BYTES (2 * HA_BYTES)
#define HNSTAGE 4
#define HGEMM_SMEM (HSTAGE_BYTES * HNSTAGE)

template <int EPI, typename OutT>
__device__ __forceinline__ void hgemm_body(
    const __half* __restrict__ A, const __half* __restrict__ Bt,
    const float* __restrict__ bias, const float* __restrict__ res,
    OutT* __restrict__ C) {
  extern __shared__ char smc[];
  const int tid = threadIdx.x;
  const int cRow = blockIdx.y, cCol = blockIdx.x;
  const int lane = tid & 31, warp = tid >> 5;
  const int lr = lane >> 2, lc = lane & 3;
  const int m0 = (warp & 1) * 64;
  const int n0 = (warp >> 1) * 32;

  const int row = tid >> 2;
  const int ch = tid & 3;

  const __half* Ap = A + (size_t)(cRow * 128 + row) * DMODEL + ch * 8;
  const __half* Bp = Bt + (size_t)(cCol * 128 + row) * DMODEL + ch * 8;

  float acc[4][4][4];
#pragma unroll
  for (int i = 0; i < 4; i++)
#pragma unroll
    for (int j = 0; j < 4; j++)
#pragma unroll
      for (int q = 0; q < 4; q++) acc[i][j][q] = 0.f;

  const int NT = DMODEL / HBK;

  auto issue = [&](int s, int t) {
    char* base = smc + s * HSTAGE_BYTES;
    const int k0 = t * HBK;
    cp_async16(base + row * HROWB + ch * 16, Ap + k0);
    cp_async16(base + (row + 64) * HROWB + ch * 16, Ap + (size_t)64 * DMODEL + k0);
    cp_async16(base + HA_BYTES + row * HROWB + ch * 16, Bp + k0);
    cp_async16(base + HA_BYTES + (row + 64) * HROWB + ch * 16,
               Bp + (size_t)64 * DMODEL + k0);
  };

#pragma unroll
  for (int s = 0; s < HNSTAGE - 1; s++) { issue(s, s); cp_commit(); }

  for (int t = 0; t < NT; t++) {
    cp_wait<HNSTAGE - 2>();
    __syncthreads();

    const char* base = smc + (t & (HNSTAGE - 1)) * HSTAGE_BYTES;
    const unsigned* Au = (const unsigned*)base;
    const unsigned* Bu = (const unsigned*)(base + HA_BYTES);

#pragma unroll
    for (int ks = 0; ks < 2; ks++) {
      const int kb = ks * 8;
      unsigned af[4][4], bf[4][2];
#pragma unroll
      for (int mt = 0; mt < 4; mt++) {
        const int m = m0 + mt * 16 + lr;
        af[mt][0] = Au[m * 20 + kb + lc];
        af[mt][1] = Au[(m + 8) * 20 + kb + lc];
        af[mt][2] = Au[m * 20 + kb + 4 + lc];
        af[mt][3] = Au[(m + 8) * 20 + kb + 4 + lc];
      }
#pragma unroll
      for (int nt = 0; nt < 4; nt++) {
        const int n = n0 + nt * 8 + lr;
        bf[nt][0] = Bu[n * 20 + kb + lc];
        bf[nt][1] = Bu[n * 20 + kb + 4 + lc];
      }
#pragma unroll
      for (int mt = 0; mt < 4; mt++)
#pragma unroll
        for (int nt = 0; nt < 4; nt++)
          mma_f16(acc[mt][nt][0], acc[mt][nt][1], acc[mt][nt][2], acc[mt][nt][3],
                  af[mt][0], af[mt][1], af[mt][2], af[mt][3],
                  bf[nt][0], bf[nt][1]);
    }

    if (t + HNSTAGE - 1 < NT)
      issue((t + HNSTAGE - 1) & (HNSTAGE - 1), t + HNSTAGE - 1);
    cp_commit();
  }

#pragma unroll
  for (int mt = 0; mt < 4; mt++) {
    const int r0 = cRow * 128 + m0 + mt * 16 + lr;
#pragma unroll
    for (int nt = 0; nt < 4; nt++) {
      const int col = cCol * 128 + n0 + nt * 8 + 2 * lc;
      const float bx = bias[col], by = bias[col + 1];
      float v0 = acc[mt][nt][0] + bx, v1 = acc[mt][nt][1] + by;
      float v2 = acc[mt][nt][2] + bx, v3 = acc[mt][nt][3] + by;
      if (EPI == 1) { v0 = gelu_f(v0); v1 = gelu_f(v1); v2 = gelu_f(v2); v3 = gelu_f(v3); }
      if (EPI == 2) {
        const float2 r4a = *(const float2*)(res + (size_t)r0 * DMODEL + col);
        const float2 r4b = *(const float2*)(res + (size_t)(r0 + 8) * DMODEL + col);
        v0 += r4a.x; v1 += r4a.y; v2 += r4b.x; v3 += r4b.y;
      }
      if (sizeof(OutT) == 2) {
        __half2 h0 = __floats2half2_rn(v0, v1);
        __half2 h1 = __floats2half2_rn(v2, v3);
        *(__half2*)((__half*)C + (size_t)r0 * DMODEL + col) = h0;
        *(__half2*)((__half*)C + (size_t)(r0 + 8) * DMODEL + col) = h1;
      } else {
        float2 o0 = {v0, v1}, o1 = {v2, v3};
        *(float2*)((float*)C + (size_t)r0 * DMODEL + col) = o0;
        *(float2*)((float*)C + (size_t)(r0 + 8) * DMODEL + col) = o1;
      }
    }
  }
}

template <int EPI, typename OutT>
__global__ void __launch_bounds__(256) hgemm_kernel(
    const __half* __restrict__ A, const __half* __restrict__ Bt,
    const float* __restrict__ bias, const float* __restrict__ res,
    OutT* __restrict__ C) {
  hgemm_body<EPI, OutT>(A, Bt, bias, res, C);
}

__global__ void __launch_bounds__(256) hqkv_kernel(
    const __half* __restrict__ A, const __half* __restrict__ wt,
    const float* __restrict__ bq, __half* __restrict__ q,
    const float* __restrict__ bk, __half* __restrict__ k,
    const float* __restrict__ bv, __half* __restrict__ v) {
  const __half* Bt;
  const float* bias;
  __half* C;
  if (blockIdx.z == 0)      { Bt = wt;                               bias = bq; C = q; }
  else if (blockIdx.z == 1) { Bt = wt + (size_t)DMODEL * DMODEL;     bias = bk; C = k; }
  else                      { Bt = wt + (size_t)2 * DMODEL * DMODEL; bias = bv; C = v; }
  hgemm_body<0, __half>(A, Bt, bias, nullptr, C);
}

// ---------------------------------------------------------------------------
// Flash attention (causal), fp16 mma, warp-local softmax, 128-row Q tile.
// 8 warps; warp w owns rows w*16..w*16+15 x ALL 64 keys of the tile.
// No cross-warp stats, no k-split epilogue. 2 barriers per k-iteration.
// smem: Qf[128][72]h @0 (18432B) | Kf[2][64][72]h @18432 | Vf[2][64][72]h @36864
// ---------------------------------------------------------------------------
#define AT_STR 72
#define AT_QOFF 0
#define AT_KOFF 18432
#define AT_VOFF 36864
#define ATTN_SMEM_H (18432 * 3)   // 55296

__global__ void __launch_bounds__(256, 2) flash_attn_h16_kernel(
    const __half* __restrict__ Q, const __half* __restrict__ K,
    const __half* __restrict__ V, __half* __restrict__ O) {
  extern __shared__ char smc[];
  const uint32_t sb = (uint32_t)__cvta_generic_to_shared(smc);
  __half* Qf = (__half*)(smc + AT_QOFF);
  __half* Kf = (__half*)(smc + AT_KOFF);
  __half* Vf = (__half*)(smc + AT_VOFF);

  const int bx = blockIdx.x, h = blockIdx.y, b = blockIdx.z;
  const int tid = threadIdx.x, lane = tid & 31, warp = tid >> 5;
  const int lr = lane >> 2, lc = lane & 3;
  const int mq = warp * 16;
  const int q0 = bx * 128;

  // ---- prologue: Q (128 rows) + KV(0) via cp.async ----
#pragma unroll
  for (int i = 0; i < 4; i++) {
    const int idx = tid + i * 256;
    const int r = idx >> 3, c = idx & 7;
    cp_async16(Qf + r * AT_STR + c * 8,
               Q + (((size_t)((b * SEQ + q0 + r) * NHEAD + h)) << 6) + c * 8);
  }
#pragma unroll
  for (int i = 0; i < 2; i++) {
    const int idx = tid + i * 256;
    const int r = idx >> 3, c = idx & 7;
    const size_t g = (((size_t)((b * SEQ + r) * NHEAD + h)) << 6) + c * 8;
    cp_async16(Kf + r * AT_STR + c * 8, K + g);
    cp_async16(Vf + r * AT_STR + c * 8, V + g);
  }
  cp_commit();
  cp_wait<0>();
  __syncthreads();

  // Q A-fragments (hoisted)
  uint32_t qa[4][4];
  {
    const int qrow = mq + (lane & 15);
#pragma unroll
    for (int ks = 0; ks < 4; ks++) {
      const uint32_t a = sb + AT_QOFF +
                         (qrow * AT_STR + ks * 16 + (lane >> 4) * 8) * 2;
      ldsm_x4(qa[ks][0], qa[ks][1], qa[ks][2], qa[ks][3], a);
    }
  }

  float oacc[8][4];
#pragma unroll
  for (int nt = 0; nt < 8; nt++)
#pragma unroll
    for (int q = 0; q < 4; q++) oacc[nt][q] = 0.f;

  const int gr0 = q0 + mq + lr, gr1 = gr0 + 8;   // global rows owned
  float mrow0 = -1e30f, mrow1 = -1e30f, lrow0 = 0.f, lrow1 = 0.f;

  const int ktmax = 2 * bx + 1;
  for (int kt = 0; kt <= ktmax; kt++) {
    const int buf = kt & 1;
    __syncthreads();  // prior-iteration reads of buf^1 complete
    if (kt < ktmax) {
      const int nb = buf ^ 1;
#pragma unroll
      for (int i = 0; i < 2; i++) {
        const int idx = tid + i * 256;
        const int r = idx >> 3, c = idx & 7;
        const size_t g =
            (((size_t)((b * SEQ + (kt + 1) * 64 + r) * NHEAD + h)) << 6) + c * 8;
        cp_async16(Kf + nb * 4608 + r * AT_STR + c * 8, K + g);
        cp_async16(Vf + nb * 4608 + r * AT_STR + c * 8, V + g);
      }
      cp_commit();
      cp_wait<1>();
    } else {
      cp_wait<0>();
    }
    __syncthreads();

    const uint32_t kbase = sb + AT_KOFF + buf * 9216;
    const uint32_t vbase = sb + AT_VOFF + buf * 9216;

    // ---- S = Q @ K^T (16 rows x 64 keys per warp) ----
    float sacc[8][4];
#pragma unroll
    for (int nt = 0; nt < 8; nt++)
#pragma unroll
      for (int q = 0; q < 4; q++) sacc[nt][q] = 0.f;
#pragma unroll
    for (int ks = 0; ks < 4; ks++) {
      uint32_t kb[8][2];
#pragma unroll
      for (int hh = 0; hh < 4; hh++) {
        const uint32_t a = kbase +
            ((hh * 16 + (lane & 15)) * AT_STR + ks * 16 + (lane >> 4) * 8) * 2;
        uint32_t t0, t1, t2, t3;
        ldsm_x4(t0, t1, t2, t3, a);
        kb[2 * hh][0] = t0; kb[2 * hh + 1][0] = t1;
        kb[2 * hh][1] = t2; kb[2 * hh + 1][1] = t3;
      }
#pragma unroll
      for (int nt = 0; nt < 8; nt++)
        mma_f16(sacc[nt][0], sacc[nt][1], sacc[nt][2], sacc[nt][3],
                qa[ks][0], qa[ks][1], qa[ks][2], qa[ks][3],
                kb[nt][0], kb[nt][1]);
    }

    // ---- scale + causal mask (registers, global indices) ----
#pragma unroll
    for (int nt = 0; nt < 8; nt++)
#pragma unroll
      for (int q = 0; q < 4; q++) sacc[nt][q] *= 0.125f;
    if (kt >= 2 * bx) {
      const int kb0 = kt * 64;
#pragma unroll
      for (int nt = 0; nt < 8; nt++) {
        const int kcol = kb0 + nt * 8 + 2 * lc;
        if (kcol > gr0) sacc[nt][0] = -1e9f;
        if (kcol + 1 > gr0) sacc[nt][1] = -1e9f;
        if (kcol > gr1) sacc[nt][2] = -1e9f;
        if (kcol + 1 > gr1) sacc[nt][3] = -1e9f;
      }
    }

    // ---- warp-local online softmax (rows gr0, gr1; full 64 keys) ----
    float tm0 = sacc[0][0], tm1 = sacc[0][2];
#pragma unroll
    for (int nt = 0; nt < 8; nt++) {
      tm0 = fmaxf(tm0, fmaxf(sacc[nt][0], sacc[nt][1]));
      tm1 = fmaxf(tm1, fmaxf(sacc[nt][2], sacc[nt][3]));
    }
    tm0 = fmaxf(tm0, __shfl_xor_sync(0xffffffffu, tm0, 1));
    tm0 = fmaxf(tm0, __shfl_xor_sync(0xffffffffu, tm0, 2));
    tm1 = fmaxf(tm1, __shfl_xor_sync(0xffffffffu, tm1, 1));
    tm1 = fmaxf(tm1, __shfl_xor_sync(0xffffffffu, tm1, 2));
    const float mnew0 = fmaxf(mrow0, tm0), mnew1 = fmaxf(mrow1, tm1);
    const float corr0 = __expf(mrow0 - mnew0), corr1 = __expf(mrow1 - mnew1);

    float ps0 = 0.f, ps1 = 0.f;
#pragma unroll
    for (int nt = 0; nt < 8; nt++) {
      sacc[nt][0] = __expf(sacc[nt][0] - mnew0);
      sacc[nt][1] = __expf(sacc[nt][1] - mnew0);
      sacc[nt][2] = __expf(sacc[nt][2] - mnew1);
      sacc[nt][3] = __expf(sacc[nt][3] - mnew1);
      ps0 += sacc[nt][0] + sacc[nt][1];
      ps1 += sacc[nt][2] + sacc[nt][3];
    }
    ps0 += __shfl_xor_sync(0xffffffffu, ps0, 1);
    ps0 += __shfl_xor_sync(0xffffffffu, ps0, 2);
    ps1 += __shfl_xor_sync(0xffffffffu, ps1, 1);
    ps1 += __shfl_xor_sync(0xffffffffu, ps1, 2);
    lrow0 = lrow0 * corr0 + ps0;
    lrow1 = lrow1 * corr1 + ps1;
    mrow0 = mnew0; mrow1 = mnew1;

    // P A-fragments straight from registers
    uint32_t pa[4][4];
#pragma unroll
    for (int ks2 = 0; ks2 < 4; ks2++) {
      pa[ks2][0] = h2u(__floats2half2_rn(sacc[2 * ks2][0], sacc[2 * ks2][1]));
      pa[ks2][1] = h2u(__floats2half2_rn(sacc[2 * ks2][2], sacc[2 * ks2][3]));
      pa[ks2][2] = h2u(__floats2half2_rn(sacc[2 * ks2 + 1][0], sacc[2 * ks2 + 1][1]));
      pa[ks2][3] = h2u(__floats2half2_rn(sacc[2 * ks2 + 1][2], sacc[2 * ks2 + 1][3]));
    }

    // ---- rescale O; O += P @ V (full 64 keys) ----
#pragma unroll
    for (int nt = 0; nt < 8; nt++) {
      oacc[nt][0] *= corr0; oacc[nt][1] *= corr0;
      oacc[nt][2] *= corr1; oacc[nt][3] *= corr1;
    }
#pragma unroll
    for (int ks2 = 0; ks2 < 4; ks2++) {
      uint32_t vb[8][2];
#pragma unroll
      for (int hh = 0; hh < 4; hh++) {
        const uint32_t a = vbase +
            ((ks2 * 16 + (lane & 15)) * AT_STR + hh * 16 + (lane >> 4) * 8) * 2;
        uint32_t t0, t1, t2, t3;
        ldsm_x4_t(t0, t1, t2, t3, a);
        vb[2 * hh][0] = t0;     vb[2 * hh][1] = t1;
        vb[2 * hh + 1][0] = t2; vb[2 * hh + 1][1] = t3;
      }
#pragma unroll
      for (int nt = 0; nt < 8; nt++)
        mma_f16(oacc[nt][0], oacc[nt][1], oacc[nt][2], oacc[nt][3],
                pa[ks2][0], pa[ks2][1], pa[ks2][2], pa[ks2][3],
                vb[nt][0], vb[nt][1]);
    }
  }

  // ---- finalize: direct per-warp store ----
  const float inv0 = 1.0f / lrow0, inv1 = 1.0f / lrow1;
#pragma unroll
  for (int nt = 0; nt < 8; nt++) {
    const int col = nt * 8 + 2 * lc;
    __half* o0 = O + (((size_t)((b * SEQ + gr0) * NHEAD + h)) << 6) + col;
    __half* o1 = O + (((size_t)((b * SEQ + gr1) * NHEAD + h)) << 6) + col;
    *(__half2*)o0 = __floats2half2_rn(oacc[nt][0] * inv0, oacc[nt][1] * inv0);
    *(__half2*)o1 = __floats2half2_rn(oacc[nt][2] * inv1, oacc[nt][3] * inv1);
  }
}

// ---------------------------------------------------------------------------
// Launch
// ---------------------------------------------------------------------------
extern "C" void kernel_launch(void* const* d_in, const int* in_sizes, int n_in,
                              void* d_out, int out_size) {
  (void)in_sizes; (void)n_in; (void)out_size;
  const float* x      = (const float*)d_in[0];
  const float* Wq     = (const float*)d_in[2];
  const float* bq     = (const float*)d_in[3];
  const float* Wk     = (const float*)d_in[4];
  const float* bk     = (const float*)d_in[5];
  const float* Wv     = (const float*)d_in[6];
  const float* bv     = (const float*)d_in[7];
  const float* Wo     = (const float*)d_in[8];
  const float* bo     = (const float*)d_in[9];
  const float* W1     = (const float*)d_in[10];
  const float* b1     = (const float*)d_in[11];
  const float* W2     = (const float*)d_in[12];
  const float* b2     = (const float*)d_in[13];
  const float* alpha1 = (const float*)d_in[14];
  const float* bias1  = (const float*)d_in[15];
  const float* alpha2 = (const float*)d_in[16];
  const float* bias2  = (const float*)d_in[17];
  float* out = (float*)d_out;

  __half *x2h, *qh, *kh, *vh, *attnh, *ffh, *wth;
  float* xmid;
  cudaGetSymbolAddress((void**)&x2h, g_x2h);
  cudaGetSymbolAddress((void**)&qh, g_qh);
  cudaGetSymbolAddress((void**)&kh, g_kh);
  cudaGetSymbolAddress((void**)&vh, g_vh);
  cudaGetSymbolAddress((void**)&attnh, g_attnh);
  cudaGetSymbolAddress((void**)&ffh, g_ffh);
  cudaGetSymbolAddress((void**)&xmid, g_xmid);
  cudaGetSymbolAddress((void**)&wth, g_wth);

  cudaFuncSetAttribute(flash_attn_h16_kernel,
                       cudaFuncAttributeMaxDynamicSharedMemorySize, ATTN_SMEM_H);
  cudaFuncSetAttribute(hgemm_kernel<1, __half>,
                       cudaFuncAttributeMaxDynamicSharedMemorySize, HGEMM_SMEM);
  cudaFuncSetAttribute(hgemm_kernel<2, float>,
                       cudaFuncAttributeMaxDynamicSharedMemorySize, HGEMM_SMEM);
  cudaFuncSetAttribute(hqkv_kernel,
                       cudaFuncAttributeMaxDynamicSharedMemorySize, HGEMM_SMEM);

  const dim3 gemm_grid(DMODEL / 128, ROWS / 128);
  const dim3 qkv_grid(DMODEL / 128, ROWS / 128, 3);

  transpose6_kernel<<<dim3(32, 32, 6), dim3(32, 8)>>>(Wq, Wk, Wv, Wo, W1, W2, wth);
  layernorm_kernel<<<ROWS, 256>>>(x, alpha1, bias1, x2h);
  hqkv_kernel<<<qkv_grid, 256, HGEMM_SMEM>>>(x2h, wth, bq, qh, bk, kh, bv, vh);
  flash_attn_h16_kernel<<<dim3(SEQ / 128, NHEAD, BATCH), 256, ATTN_SMEM_H>>>(
      qh, kh, vh, attnh);
  hgemm_kernel<2, float><<<gemm_grid, 256, HGEMM_SMEM>>>(
      attnh, wth + (size_t)3 * DMODEL * DMODEL, bo, x, xmid);
  layernorm_kernel<<<ROWS, 256>>>(xmid, alpha2, bias2, x2h);
  hgemm_kernel<1, __half><<<gemm_grid, 256, HGEMM_SMEM>>>(
      x2h, wth + (size_t)4 * DMODEL * DMODEL, b1, nullptr, ffh);
  hgemm_kernel<2, float><<<gemm_grid, 256, HGEMM_SMEM>>>(
      ffh, wth + (size_t)5 * DMODEL * DMODEL, b2, xmid, out);
}

// round 16
// speedup vs baseline: 1.2335x; 1.0748x over previous
#include <cuda_runtime.h>
#include <cuda_fp16.h>
#include <math.h>
#include <stdint.h>

// Problem constants
#define BATCH 4
#define SEQ 2048
#define DMODEL 1024
#define NHEAD 16
#define ROWS (BATCH * SEQ)   // 8192

// ---------------------------------------------------------------------------
// Scratch (device globals; no allocation allowed)
// ---------------------------------------------------------------------------
__device__ __half g_x2h[ROWS * DMODEL];
__device__ __half g_qh[ROWS * DMODEL];
__device__ __half g_kh[ROWS * DMODEL];
__device__ __half g_vh[ROWS * DMODEL];
__device__ __half g_attnh[ROWS * DMODEL];
__device__ __half g_ffh[ROWS * DMODEL];
__device__ float g_xmid[ROWS * DMODEL];
__device__ __half g_wth[6 * DMODEL * DMODEL];   // transposed fp16 weights [N][K]

// ---------------------------------------------------------------------------
// helpers
// ---------------------------------------------------------------------------
__device__ __forceinline__ void mma_f16(
    float& c0, float& c1, float& c2, float& c3,
    unsigned a0, unsigned a1, unsigned a2, unsigned a3,
    unsigned b0, unsigned b1) {
  asm("mma.sync.aligned.m16n8k16.row.col.f32.f16.f16.f32 "
      "{%0,%1,%2,%3}, {%4,%5,%6,%7}, {%8,%9}, {%0,%1,%2,%3};"
      : "+f"(c0), "+f"(c1), "+f"(c2), "+f"(c3)
      : "r"(a0), "r"(a1), "r"(a2), "r"(a3), "r"(b0), "r"(b1));
}

__device__ __forceinline__ void ldsm_x4(uint32_t& r0, uint32_t& r1,
                                        uint32_t& r2, uint32_t& r3, uint32_t a) {
  asm volatile("ldmatrix.sync.aligned.m8n8.x4.shared.b16 {%0,%1,%2,%3}, [%4];"
               : "=r"(r0), "=r"(r1), "=r"(r2), "=r"(r3) : "r"(a));
}
__device__ __forceinline__ void ldsm_x4_t(uint32_t& r0, uint32_t& r1,
                                          uint32_t& r2, uint32_t& r3, uint32_t a) {
  asm volatile("ldmatrix.sync.aligned.m8n8.x4.trans.shared.b16 {%0,%1,%2,%3}, [%4];"
               : "=r"(r0), "=r"(r1), "=r"(r2), "=r"(r3) : "r"(a));
}

__device__ __forceinline__ void cp_async16(void* smem_dst, const void* gmem_src) {
  unsigned s = (unsigned)__cvta_generic_to_shared(smem_dst);
  asm volatile("cp.async.ca.shared.global [%0], [%1], 16;\n" ::"r"(s),
               "l"(gmem_src));
}
__device__ __forceinline__ void cp_commit() {
  asm volatile("cp.async.commit_group;\n" ::);
}
template <int N>
__device__ __forceinline__ void cp_wait() {
  asm volatile("cp.async.wait_group %0;\n" ::"n"(N));
}

__device__ __forceinline__ float gelu_f(float v) {
  float t = tanhf(0.7978845608028654f * (v + 0.044715f * v * v * v));
  return 0.5f * v * (1.0f + t);
}

__device__ __forceinline__ unsigned h2u(__half2 h) { return *(unsigned*)&h; }

// ---------------------------------------------------------------------------
// LayerNorm: f32 in -> fp16 out
// ---------------------------------------------------------------------------
__global__ void __launch_bounds__(256) layernorm_kernel(
    const float* __restrict__ x, const float* __restrict__ alpha,
    const float* __restrict__ beta, __half* __restrict__ y) {
  __shared__ float red[8];
  __shared__ float bcast;
  const int row = blockIdx.x;
  const int tid = threadIdx.x;
  const float* xp = x + (size_t)row * DMODEL;

  float4 v = *(const float4*)(xp + tid * 4);
  float s = v.x + v.y + v.z + v.w;
#pragma unroll
  for (int o = 16; o; o >>= 1) s += __shfl_xor_sync(0xffffffffu, s, o);
  if ((tid & 31) == 0) red[tid >> 5] = s;
  __syncthreads();
  if (tid == 0) {
    float t = 0.f;
#pragma unroll
    for (int i = 0; i < 8; i++) t += red[i];
    bcast = t;
  }
  __syncthreads();
  const float mean = bcast * (1.0f / (float)DMODEL);
  __syncthreads();

  const float dx = v.x - mean, dy = v.y - mean, dz = v.z - mean, dw = v.w - mean;
  float sq = dx * dx + dy * dy + dz * dz + dw * dw;
#pragma unroll
  for (int o = 16; o; o >>= 1) sq += __shfl_xor_sync(0xffffffffu, sq, o);
  if ((tid & 31) == 0) red[tid >> 5] = sq;
  __syncthreads();
  if (tid == 0) {
    float t = 0.f;
#pragma unroll
    for (int i = 0; i < 8; i++) t += red[i];
    bcast = t;
  }
  __syncthreads();
  const float var = bcast * (1.0f / (float)(DMODEL - 1));
  const float sc = 1.0f / (sqrtf(var) + 1e-6f);

  const float4 a4 = *(const float4*)(alpha + tid * 4);
  const float4 b4 = *(const float4*)(beta + tid * 4);
  __half2 h01 = __floats2half2_rn(a4.x * dx * sc + b4.x, a4.y * dy * sc + b4.y);
  __half2 h23 = __floats2half2_rn(a4.z * dz * sc + b4.z, a4.w * dw * sc + b4.w);
  uint2 u = {h2u(h01), h2u(h23)};
  *(uint2*)(y + (size_t)row * DMODEL + tid * 4) = u;
}

// ---------------------------------------------------------------------------
// Weight transpose prepass: Wt[n][k] = (half)W[k][n]
// ---------------------------------------------------------------------------
__global__ void __launch_bounds__(256) transpose6_kernel(
    const float* __restrict__ Wq, const float* __restrict__ Wk,
    const float* __restrict__ Wv, const float* __restrict__ Wo,
    const float* __restrict__ W1, const float* __restrict__ W2,
    __half* __restrict__ wt) {
  const float* src;
  switch (blockIdx.z) {
    case 0: src = Wq; break;
    case 1: src = Wk; break;
    case 2: src = Wv; break;
    case 3: src = Wo; break;
    case 4: src = W1; break;
    default: src = W2; break;
  }
  __half* dst = wt + (size_t)blockIdx.z * DMODEL * DMODEL;
  __shared__ float tl[32][33];
  const int tx = threadIdx.x, ty = threadIdx.y;
  const int x = blockIdx.x * 32 + tx;
  const int y = blockIdx.y * 32 + ty;
#pragma unroll
  for (int i = 0; i < 32; i += 8)
    tl[ty + i][tx] = src[(size_t)(y + i) * DMODEL + x];
  __syncthreads();
  const int x2 = blockIdx.y * 32 + tx;
  const int y2 = blockIdx.x * 32 + ty;
#pragma unroll
  for (int i = 0; i < 32; i += 8)
    dst[(size_t)(y2 + i) * DMODEL + x2] = __float2half_rn(tl[tx][ty + i]);
}

// ---------------------------------------------------------------------------
// fp16 TC GEMM: R12 pipeline (BK=32, 4-stage, HROWB=80) with ldmatrix
// fragment loads (12 LDSM vs 48 LDS.32 per warp per ktile).
// Row stride 80B = 20 words: ldmatrix phase banks 20r mod 32 distinct.
// ---------------------------------------------------------------------------
#define HBK 32
#define HROWB 80
#define HA_BYTES (128 * HROWB)
#define HSTAGE_BYTES (2 * HA_BYTES)
#define HNSTAGE 4
#define HGEMM_SMEM (HSTAGE_BYTES * HNSTAGE)

template <int EPI, typename OutT>
__device__ __forceinline__ void hgemm_body(
    const __half* __restrict__ A, const __half* __restrict__ Bt,
    const float* __restrict__ bias, const float* __restrict__ res,
    OutT* __restrict__ C) {
  extern __shared__ char smc[];
  const uint32_t sb = (uint32_t)__cvta_generic_to_shared(smc);
  const int tid = threadIdx.x;
  const int cRow = blockIdx.y, cCol = blockIdx.x;
  const int lane = tid & 31, warp = tid >> 5;
  const int lr = lane >> 2, lc = lane & 3;
  const int m0 = (warp & 1) * 64;
  const int n0 = (warp >> 1) * 32;

  const int row = tid >> 2;
  const int ch = tid & 3;

  const __half* Ap = A + (size_t)(cRow * 128 + row) * DMODEL + ch * 8;
  const __half* Bp = Bt + (size_t)(cCol * 128 + row) * DMODEL + ch * 8;

  float acc[4][4][4];
#pragma unroll
  for (int i = 0; i < 4; i++)
#pragma unroll
    for (int j = 0; j < 4; j++)
#pragma unroll
      for (int q = 0; q < 4; q++) acc[i][j][q] = 0.f;

  const int NT = DMODEL / HBK;

  auto issue = [&](int s, int t) {
    char* base = smc + s * HSTAGE_BYTES;
    const int k0 = t * HBK;
    cp_async16(base + row * HROWB + ch * 16, Ap + k0);
    cp_async16(base + (row + 64) * HROWB + ch * 16, Ap + (size_t)64 * DMODEL + k0);
    cp_async16(base + HA_BYTES + row * HROWB + ch * 16, Bp + k0);
    cp_async16(base + HA_BYTES + (row + 64) * HROWB + ch * 16,
               Bp + (size_t)64 * DMODEL + k0);
  };

#pragma unroll
  for (int s = 0; s < HNSTAGE - 1; s++) { issue(s, s); cp_commit(); }

  // ldmatrix lane-invariant offsets
  const uint32_t aoff = (m0 + (lane & 15)) * HROWB + (lane >> 4) * 16;
  const uint32_t boff =
      (n0 + (lane & 7) + ((lane >> 4) & 1) * 8) * HROWB + ((lane >> 3) & 1) * 16;

  for (int t = 0; t < NT; t++) {
    cp_wait<HNSTAGE - 2>();
    __syncthreads();

    const uint32_t sA = sb + (t & (HNSTAGE - 1)) * HSTAGE_BYTES;
    const uint32_t sB = sA + HA_BYTES;

#pragma unroll
    for (int ks = 0; ks < 2; ks++) {
      uint32_t af[4][4], bf[4][2];
#pragma unroll
      for (int mt = 0; mt < 4; mt++)
        ldsm_x4(af[mt][0], af[mt][1], af[mt][2], af[mt][3],
                sA + aoff + mt * 16 * HROWB + ks * 32);
#pragma unroll
      for (int ntp = 0; ntp < 2; ntp++) {
        uint32_t t0, t1, t2, t3;
        ldsm_x4(t0, t1, t2, t3, sB + boff + ntp * 16 * HROWB + ks * 32);
        bf[2 * ntp][0] = t0;     bf[2 * ntp][1] = t1;
        bf[2 * ntp + 1][0] = t2; bf[2 * ntp + 1][1] = t3;
      }
#pragma unroll
      for (int mt = 0; mt < 4; mt++)
#pragma unroll
        for (int nt = 0; nt < 4; nt++)
          mma_f16(acc[mt][nt][0], acc[mt][nt][1], acc[mt][nt][2], acc[mt][nt][3],
                  af[mt][0], af[mt][1], af[mt][2], af[mt][3],
                  bf[nt][0], bf[nt][1]);
    }

    if (t + HNSTAGE - 1 < NT)
      issue((t + HNSTAGE - 1) & (HNSTAGE - 1), t + HNSTAGE - 1);
    cp_commit();
  }

#pragma unroll
  for (int mt = 0; mt < 4; mt++) {
    const int r0 = cRow * 128 + m0 + mt * 16 + lr;
#pragma unroll
    for (int nt = 0; nt < 4; nt++) {
      const int col = cCol * 128 + n0 + nt * 8 + 2 * lc;
      const float bx = bias[col], by = bias[col + 1];
      float v0 = acc[mt][nt][0] + bx, v1 = acc[mt][nt][1] + by;
      float v2 = acc[mt][nt][2] + bx, v3 = acc[mt][nt][3] + by;
      if (EPI == 1) { v0 = gelu_f(v0); v1 = gelu_f(v1); v2 = gelu_f(v2); v3 = gelu_f(v3); }
      if (EPI == 2) {
        const float2 r4a = *(const float2*)(res + (size_t)r0 * DMODEL + col);
        const float2 r4b = *(const float2*)(res + (size_t)(r0 + 8) * DMODEL + col);
        v0 += r4a.x; v1 += r4a.y; v2 += r4b.x; v3 += r4b.y;
      }
      if (sizeof(OutT) == 2) {
        __half2 h0 = __floats2half2_rn(v0, v1);
        __half2 h1 = __floats2half2_rn(v2, v3);
        *(__half2*)((__half*)C + (size_t)r0 * DMODEL + col) = h0;
        *(__half2*)((__half*)C + (size_t)(r0 + 8) * DMODEL + col) = h1;
      } else {
        float2 o0 = {v0, v1}, o1 = {v2, v3};
        *(float2*)((float*)C + (size_t)r0 * DMODEL + col) = o0;
        *(float2*)((float*)C + (size_t)(r0 + 8) * DMODEL + col) = o1;
      }
    }
  }
}

template <int EPI, typename OutT>
__global__ void __launch_bounds__(256) hgemm_kernel(
    const __half* __restrict__ A, const __half* __restrict__ Bt,
    const float* __restrict__ bias, const float* __restrict__ res,
    OutT* __restrict__ C) {
  hgemm_body<EPI, OutT>(A, Bt, bias, res, C);
}

__global__ void __launch_bounds__(256) hqkv_kernel(
    const __half* __restrict__ A, const __half* __restrict__ wt,
    const float* __restrict__ bq, __half* __restrict__ q,
    const float* __restrict__ bk, __half* __restrict__ k,
    const float* __restrict__ bv, __half* __restrict__ v) {
  const __half* Bt;
  const float* bias;
  __half* C;
  if (blockIdx.z == 0)      { Bt = wt;                               bias = bq; C = q; }
  else if (blockIdx.z == 1) { Bt = wt + (size_t)DMODEL * DMODEL;     bias = bk; C = k; }
  else                      { Bt = wt + (size_t)2 * DMODEL * DMODEL; bias = bv; C = v; }
  hgemm_body<0, __half>(A, Bt, bias, nullptr, C);
}

// ---------------------------------------------------------------------------
// Flash attention (causal), fp16 mma, warp-local softmax, 128-row Q tile.
// (R15 proven version, unchanged)
// ---------------------------------------------------------------------------
#define AT_STR 72
#define AT_QOFF 0
#define AT_KOFF 18432
#define AT_VOFF 36864
#define ATTN_SMEM_H (18432 * 3)   // 55296

__global__ void __launch_bounds__(256, 2) flash_attn_h16_kernel(
    const __half* __restrict__ Q, const __half* __restrict__ K,
    const __half* __restrict__ V, __half* __restrict__ O) {
  extern __shared__ char smc[];
  const uint32_t sb = (uint32_t)__cvta_generic_to_shared(smc);
  __half* Qf = (__half*)(smc + AT_QOFF);
  __half* Kf = (__half*)(smc + AT_KOFF);
  __half* Vf = (__half*)(smc + AT_VOFF);

  const int bx = blockIdx.x, h = blockIdx.y, b = blockIdx.z;
  const int tid = threadIdx.x, lane = tid & 31, warp = tid >> 5;
  const int lr = lane >> 2, lc = lane & 3;
  const int mq = warp * 16;
  const int q0 = bx * 128;

#pragma unroll
  for (int i = 0; i < 4; i++) {
    const int idx = tid + i * 256;
    const int r = idx >> 3, c = idx & 7;
    cp_async16(Qf + r * AT_STR + c * 8,
               Q + (((size_t)((b * SEQ + q0 + r) * NHEAD + h)) << 6) + c * 8);
  }
#pragma unroll
  for (int i = 0; i < 2; i++) {
    const int idx = tid + i * 256;
    const int r = idx >> 3, c = idx & 7;
    const size_t g = (((size_t)((b * SEQ + r) * NHEAD + h)) << 6) + c * 8;
    cp_async16(Kf + r * AT_STR + c * 8, K + g);
    cp_async16(Vf + r * AT_STR + c * 8, V + g);
  }
  cp_commit();
  cp_wait<0>();
  __syncthreads();

  uint32_t qa[4][4];
  {
    const int qrow = mq + (lane & 15);
#pragma unroll
    for (int ks = 0; ks < 4; ks++) {
      const uint32_t a = sb + AT_QOFF +
                         (qrow * AT_STR + ks * 16 + (lane >> 4) * 8) * 2;
      ldsm_x4(qa[ks][0], qa[ks][1], qa[ks][2], qa[ks][3], a);
    }
  }

  float oacc[8][4];
#pragma unroll
  for (int nt = 0; nt < 8; nt++)
#pragma unroll
    for (int q = 0; q < 4; q++) oacc[nt][q] = 0.f;

  const int gr0 = q0 + mq + lr, gr1 = gr0 + 8;
  float mrow0 = -1e30f, mrow1 = -1e30f, lrow0 = 0.f, lrow1 = 0.f;

  const int ktmax = 2 * bx + 1;
  for (int kt = 0; kt <= ktmax; kt++) {
    const int buf = kt & 1;
    __syncthreads();
    if (kt < ktmax) {
      const int nb = buf ^ 1;
#pragma unroll
      for (int i = 0; i < 2; i++) {
        const int idx = tid + i * 256;
        const int r = idx >> 3, c = idx & 7;
        const size_t g =
            (((size_t)((b * SEQ + (kt + 1) * 64 + r) * NHEAD + h)) << 6) + c * 8;
        cp_async16(Kf + nb * 4608 + r * AT_STR + c * 8, K + g);
        cp_async16(Vf + nb * 4608 + r * AT_STR + c * 8, V + g);
      }
      cp_commit();
      cp_wait<1>();
    } else {
      cp_wait<0>();
    }
    __syncthreads();

    const uint32_t kbase = sb + AT_KOFF + buf * 9216;
    const uint32_t vbase = sb + AT_VOFF + buf * 9216;

    float sacc[8][4];
#pragma unroll
    for (int nt = 0; nt < 8; nt++)
#pragma unroll
      for (int q = 0; q < 4; q++) sacc[nt][q] = 0.f;
#pragma unroll
    for (int ks = 0; ks < 4; ks++) {
      uint32_t kb[8][2];
#pragma unroll
      for (int hh = 0; hh < 4; hh++) {
        const uint32_t a = kbase +
            ((hh * 16 + (lane & 15)) * AT_STR + ks * 16 + (lane >> 4) * 8) * 2;
        uint32_t t0, t1, t2, t3;
        ldsm_x4(t0, t1, t2, t3, a);
        kb[2 * hh][0] = t0; kb[2 * hh + 1][0] = t1;
        kb[2 * hh][1] = t2; kb[2 * hh + 1][1] = t3;
      }
#pragma unroll
      for (int nt = 0; nt < 8; nt++)
        mma_f16(sacc[nt][0], sacc[nt][1], sacc[nt][2], sacc[nt][3],
                qa[ks][0], qa[ks][1], qa[ks][2], qa[ks][3],
                kb[nt][0], kb[nt][1]);
    }

#pragma unroll
    for (int nt = 0; nt < 8; nt++)
#pragma unroll
      for (int q = 0; q < 4; q++) sacc[nt][q] *= 0.125f;
    if (kt >= 2 * bx) {
      const int kb0 = kt * 64;
#pragma unroll
      for (int nt = 0; nt < 8; nt++) {
        const int kcol = kb0 + nt * 8 + 2 * lc;
        if (kcol > gr0) sacc[nt][0] = -1e9f;
        if (kcol + 1 > gr0) sacc[nt][1] = -1e9f;
        if (kcol > gr1) sacc[nt][2] = -1e9f;
        if (kcol + 1 > gr1) sacc[nt][3] = -1e9f;
      }
    }

    float tm0 = sacc[0][0], tm1 = sacc[0][2];
#pragma unroll
    for (int nt = 0; nt < 8; nt++) {
      tm0 = fmaxf(tm0, fmaxf(sacc[nt][0], sacc[nt][1]));
      tm1 = fmaxf(tm1, fmaxf(sacc[nt][2], sacc[nt][3]));
    }
    tm0 = fmaxf(tm0, __shfl_xor_sync(0xffffffffu, tm0, 1));
    tm0 = fmaxf(tm0, __shfl_xor_sync(0xffffffffu, tm0, 2));
    tm1 = fmaxf(tm1, __shfl_xor_sync(0xffffffffu, tm1, 1));
    tm1 = fmaxf(tm1, __shfl_xor_sync(0xffffffffu, tm1, 2));
    const float mnew0 = fmaxf(mrow0, tm0), mnew1 = fmaxf(mrow1, tm1);
    const float corr0 = __expf(mrow0 - mnew0), corr1 = __expf(mrow1 - mnew1);

    float ps0 = 0.f, ps1 = 0.f;
#pragma unroll
    for (int nt = 0; nt < 8; nt++) {
      sacc[nt][0] = __expf(sacc[nt][0] - mnew0);
      sacc[nt][1] = __expf(sacc[nt][1] - mnew0);
      sacc[nt][2] = __expf(sacc[nt][2] - mnew1);
      sacc[nt][3] = __expf(sacc[nt][3] - mnew1);
      ps0 += sacc[nt][0] + sacc[nt][1];
      ps1 += sacc[nt][2] + sacc[nt][3];
    }
    ps0 += __shfl_xor_sync(0xffffffffu, ps0, 1);
    ps0 += __shfl_xor_sync(0xffffffffu, ps0, 2);
    ps1 += __shfl_xor_sync(0xffffffffu, ps1, 1);
    ps1 += __shfl_xor_sync(0xffffffffu, ps1, 2);
    lrow0 = lrow0 * corr0 + ps0;
    lrow1 = lrow1 * corr1 + ps1;
    mrow0 = mnew0; mrow1 = mnew1;

    uint32_t pa[4][4];
#pragma unroll
    for (int ks2 = 0; ks2 < 4; ks2++) {
      pa[ks2][0] = h2u(__floats2half2_rn(sacc[2 * ks2][0], sacc[2 * ks2][1]));
      pa[ks2][1] = h2u(__floats2half2_rn(sacc[2 * ks2][2], sacc[2 * ks2][3]));
      pa[ks2][2] = h2u(__floats2half2_rn(sacc[2 * ks2 + 1][0], sacc[2 * ks2 + 1][1]));
      pa[ks2][3] = h2u(__floats2half2_rn(sacc[2 * ks2 + 1][2], sacc[2 * ks2 + 1][3]));
    }

#pragma unroll
    for (int nt = 0; nt < 8; nt++) {
      oacc[nt][0] *= corr0; oacc[nt][1] *= corr0;
      oacc[nt][2] *= corr1; oacc[nt][3] *= corr1;
    }
#pragma unroll
    for (int ks2 = 0; ks2 < 4; ks2++) {
      uint32_t vb[8][2];
#pragma unroll
      for (int hh = 0; hh < 4; hh++) {
        const uint32_t a = vbase +
            ((ks2 * 16 + (lane & 15)) * AT_STR + hh * 16 + (lane >> 4) * 8) * 2;
        uint32_t t0, t1, t2, t3;
        ldsm_x4_t(t0, t1, t2, t3, a);
        vb[2 * hh][0] = t0;     vb[2 * hh][1] = t1;
        vb[2 * hh + 1][0] = t2; vb[2 * hh + 1][1] = t3;
      }
#pragma unroll
      for (int nt = 0; nt < 8; nt++)
        mma_f16(oacc[nt][0], oacc[nt][1], oacc[nt][2], oacc[nt][3],
                pa[ks2][0], pa[ks2][1], pa[ks2][2], pa[ks2][3],
                vb[nt][0], vb[nt][1]);
    }
  }

  const float inv0 = 1.0f / lrow0, inv1 = 1.0f / lrow1;
#pragma unroll
  for (int nt = 0; nt < 8; nt++) {
    const int col = nt * 8 + 2 * lc;
    __half* o0 = O + (((size_t)((b * SEQ + gr0) * NHEAD + h)) << 6) + col;
    __half* o1 = O + (((size_t)((b * SEQ + gr1) * NHEAD + h)) << 6) + col;
    *(__half2*)o0 = __floats2half2_rn(oacc[nt][0] * inv0, oacc[nt][1] * inv0);
    *(__half2*)o1 = __floats2half2_rn(oacc[nt][2] * inv1, oacc[nt][3] * inv1);
  }
}

// ---------------------------------------------------------------------------
// Launch
// ---------------------------------------------------------------------------
extern "C" void kernel_launch(void* const* d_in, const int* in_sizes, int n_in,
                              void* d_out, int out_size) {
  (void)in_sizes; (void)n_in; (void)out_size;
  const float* x      = (const float*)d_in[0];
  const float* Wq     = (const float*)d_in[2];
  const float* bq     = (const float*)d_in[3];
  const float* Wk     = (const float*)d_in[4];
  const float* bk     = (const float*)d_in[5];
  const float* Wv     = (const float*)d_in[6];
  const float* bv     = (const float*)d_in[7];
  const float* Wo     = (const float*)d_in[8];
  const float* bo     = (const float*)d_in[9];
  const float* W1     = (const float*)d_in[10];
  const float* b1     = (const float*)d_in[11];
  const float* W2     = (const float*)d_in[12];
  const float* b2     = (const float*)d_in[13];
  const float* alpha1 = (const float*)d_in[14];
  const float* bias1  = (const float*)d_in[15];
  const float* alpha2 = (const float*)d_in[16];
  const float* bias2  = (const float*)d_in[17];
  float* out = (float*)d_out;

  __half *x2h, *qh, *kh, *vh, *attnh, *ffh, *wth;
  float* xmid;
  cudaGetSymbolAddress((void**)&x2h, g_x2h);
  cudaGetSymbolAddress((void**)&qh, g_qh);
  cudaGetSymbolAddress((void**)&kh, g_kh);
  cudaGetSymbolAddress((void**)&vh, g_vh);
  cudaGetSymbolAddress((void**)&attnh, g_attnh);
  cudaGetSymbolAddress((void**)&ffh, g_ffh);
  cudaGetSymbolAddress((void**)&xmid, g_xmid);
  cudaGetSymbolAddress((void**)&wth, g_wth);

  cudaFuncSetAttribute(flash_attn_h16_kernel,
                       cudaFuncAttributeMaxDynamicSharedMemorySize, ATTN_SMEM_H);
  cudaFuncSetAttribute(hgemm_kernel<1, __half>,
                       cudaFuncAttributeMaxDynamicSharedMemorySize, HGEMM_SMEM);
  cudaFuncSetAttribute(hgemm_kernel<2, float>,
                       cudaFuncAttributeMaxDynamicSharedMemorySize, HGEMM_SMEM);
  cudaFuncSetAttribute(hqkv_kernel,
                       cudaFuncAttributeMaxDynamicSharedMemorySize, HGEMM_SMEM);

  const dim3 gemm_grid(DMODEL / 128, ROWS / 128);
  const dim3 qkv_grid(DMODEL / 128, ROWS / 128, 3);

  transpose6_kernel<<<dim3(32, 32, 6), dim3(32, 8)>>>(Wq, Wk, Wv, Wo, W1, W2, wth);
  layernorm_kernel<<<ROWS, 256>>>(x, alpha1, bias1, x2h);
  hqkv_kernel<<<qkv_grid, 256, HGEMM_SMEM>>>(x2h, wth, bq, qh, bk, kh, bv, vh);
  flash_attn_h16_kernel<<<dim3(SEQ / 128, NHEAD, BATCH), 256, ATTN_SMEM_H>>>(
      qh, kh, vh, attnh);
  hgemm_kernel<2, float><<<gemm_grid, 256, HGEMM_SMEM>>>(
      attnh, wth + (size_t)3 * DMODEL * DMODEL, bo, x, xmid);
  layernorm_kernel<<<ROWS, 256>>>(xmid, alpha2, bias2, x2h);
  hgemm_kernel<1, __half><<<gemm_grid, 256, HGEMM_SMEM>>>(
      x2h, wth + (size_t)4 * DMODEL * DMODEL, b1, nullptr, ffh);
  hgemm_kernel<2, float><<<gemm_grid, 256, HGEMM_SMEM>>>(
      ffh, wth + (size_t)5 * DMODEL * DMODEL, b2, xmid, out);
}

// round 17
// speedup vs baseline: 1.2680x; 1.0280x over previous
#include <cuda_runtime.h>
#include <cuda_fp16.h>
#include <math.h>
#include <stdint.h>

// Problem constants
#define BATCH 4
#define SEQ 2048
#define DMODEL 1024
#define NHEAD 16
#define ROWS (BATCH * SEQ)   // 8192

// ---------------------------------------------------------------------------
// Scratch (device globals; no allocation allowed)
// ---------------------------------------------------------------------------
__device__ __half g_x2h[ROWS * DMODEL];
__device__ __half g_qh[ROWS * DMODEL];
__device__ __half g_kh[ROWS * DMODEL];
__device__ __half g_vh[ROWS * DMODEL];
__device__ __half g_attnh[ROWS * DMODEL];
__device__ __half g_ffh[ROWS * DMODEL];
__device__ float g_xmid[ROWS * DMODEL];
__device__ __half g_wth[6 * DMODEL * DMODEL];   // transposed fp16 weights [N][K]

// ---------------------------------------------------------------------------
// helpers
// ---------------------------------------------------------------------------
__device__ __forceinline__ void mma_f16(
    float& c0, float& c1, float& c2, float& c3,
    unsigned a0, unsigned a1, unsigned a2, unsigned a3,
    unsigned b0, unsigned b1) {
  asm("mma.sync.aligned.m16n8k16.row.col.f32.f16.f16.f32 "
      "{%0,%1,%2,%3}, {%4,%5,%6,%7}, {%8,%9}, {%0,%1,%2,%3};"
      : "+f"(c0), "+f"(c1), "+f"(c2), "+f"(c3)
      : "r"(a0), "r"(a1), "r"(a2), "r"(a3), "r"(b0), "r"(b1));
}

__device__ __forceinline__ void ldsm_x4(uint32_t& r0, uint32_t& r1,
                                        uint32_t& r2, uint32_t& r3, uint32_t a) {
  asm volatile("ldmatrix.sync.aligned.m8n8.x4.shared.b16 {%0,%1,%2,%3}, [%4];"
               : "=r"(r0), "=r"(r1), "=r"(r2), "=r"(r3) : "r"(a));
}
__device__ __forceinline__ void ldsm_x4_t(uint32_t& r0, uint32_t& r1,
                                          uint32_t& r2, uint32_t& r3, uint32_t a) {
  asm volatile("ldmatrix.sync.aligned.m8n8.x4.trans.shared.b16 {%0,%1,%2,%3}, [%4];"
               : "=r"(r0), "=r"(r1), "=r"(r2), "=r"(r3) : "r"(a));
}

// L2-cached (L1-bypass) async copy — loads here are L2-reuse dominated
__device__ __forceinline__ void cp_async16(void* smem_dst, const void* gmem_src) {
  unsigned s = (unsigned)__cvta_generic_to_shared(smem_dst);
  asm volatile("cp.async.cg.shared.global [%0], [%1], 16;\n" ::"r"(s),
               "l"(gmem_src));
}
__device__ __forceinline__ void cp_commit() {
  asm volatile("cp.async.commit_group;\n" ::);
}
template <int N>
__device__ __forceinline__ void cp_wait() {
  asm volatile("cp.async.wait_group %0;\n" ::"n"(N));
}

__device__ __forceinline__ float gelu_f(float v) {
  float t = tanhf(0.7978845608028654f * (v + 0.044715f * v * v * v));
  return 0.5f * v * (1.0f + t);
}

__device__ __forceinline__ unsigned h2u(__half2 h) { return *(unsigned*)&h; }

// ---------------------------------------------------------------------------
// LayerNorm: f32 in -> fp16 out
// ---------------------------------------------------------------------------
__global__ void __launch_bounds__(256) layernorm_kernel(
    const float* __restrict__ x, const float* __restrict__ alpha,
    const float* __restrict__ beta, __half* __restrict__ y) {
  __shared__ float red[8];
  __shared__ float bcast;
  const int row = blockIdx.x;
  const int tid = threadIdx.x;
  const float* xp = x + (size_t)row * DMODEL;

  float4 v = *(const float4*)(xp + tid * 4);
  float s = v.x + v.y + v.z + v.w;
#pragma unroll
  for (int o = 16; o; o >>= 1) s += __shfl_xor_sync(0xffffffffu, s, o);
  if ((tid & 31) == 0) red[tid >> 5] = s;
  __syncthreads();
  if (tid == 0) {
    float t = 0.f;
#pragma unroll
    for (int i = 0; i < 8; i++) t += red[i];
    bcast = t;
  }
  __syncthreads();
  const float mean = bcast * (1.0f / (float)DMODEL);
  __syncthreads();

  const float dx = v.x - mean, dy = v.y - mean, dz = v.z - mean, dw = v.w - mean;
  float sq = dx * dx + dy * dy + dz * dz + dw * dw;
#pragma unroll
  for (int o = 16; o; o >>= 1) sq += __shfl_xor_sync(0xffffffffu, sq, o);
  if ((tid & 31) == 0) red[tid >> 5] = sq;
  __syncthreads();
  if (tid == 0) {
    float t = 0.f;
#pragma unroll
    for (int i = 0; i < 8; i++) t += red[i];
    bcast = t;
  }
  __syncthreads();
  const float var = bcast * (1.0f / (float)(DMODEL - 1));
  const float sc = 1.0f / (sqrtf(var) + 1e-6f);

  const float4 a4 = *(const float4*)(alpha + tid * 4);
  const float4 b4 = *(const float4*)(beta + tid * 4);
  __half2 h01 = __floats2half2_rn(a4.x * dx * sc + b4.x, a4.y * dy * sc + b4.y);
  __half2 h23 = __floats2half2_rn(a4.z * dz * sc + b4.z, a4.w * dw * sc + b4.w);
  uint2 u = {h2u(h01), h2u(h23)};
  *(uint2*)(y + (size_t)row * DMODEL + tid * 4) = u;
}

// ---------------------------------------------------------------------------
// Weight transpose prepass: Wt[n][k] = (half)W[k][n]
// ---------------------------------------------------------------------------
__global__ void __launch_bounds__(256) transpose6_kernel(
    const float* __restrict__ Wq, const float* __restrict__ Wk,
    const float* __restrict__ Wv, const float* __restrict__ Wo,
    const float* __restrict__ W1, const float* __restrict__ W2,
    __half* __restrict__ wt) {
  const float* src;
  switch (blockIdx.z) {
    case 0: src = Wq; break;
    case 1: src = Wk; break;
    case 2: src = Wv; break;
    case 3: src = Wo; break;
    case 4: src = W1; break;
    default: src = W2; break;
  }
  __half* dst = wt + (size_t)blockIdx.z * DMODEL * DMODEL;
  __shared__ float tl[32][33];
  const int tx = threadIdx.x, ty = threadIdx.y;
  const int x = blockIdx.x * 32 + tx;
  const int y = blockIdx.y * 32 + ty;
#pragma unroll
  for (int i = 0; i < 32; i += 8)
    tl[ty + i][tx] = src[(size_t)(y + i) * DMODEL + x];
  __syncthreads();
  const int x2 = blockIdx.y * 32 + tx;
  const int y2 = blockIdx.x * 32 + ty;
#pragma unroll
  for (int i = 0; i < 32; i += 8)
    dst[(size_t)(y2 + i) * DMODEL + x2] = __float2half_rn(tl[tx][ty + i]);
}

// ---------------------------------------------------------------------------
// fp16 TC GEMM: R16 proven (BK=32, 4-stage, HROWB=80, ldmatrix fragments)
// ---------------------------------------------------------------------------
#define HBK 32
#define HROWB 80
#define HA_BYTES (128 * HROWB)
#define HSTAGE_BYTES (2 * HA_BYTES)
#define HNSTAGE 4
#define HGEMM_SMEM (HSTAGE_BYTES * HNSTAGE)

template <int EPI, typename OutT>
__device__ __forceinline__ void hgemm_body(
    const __half* __restrict__ A, const __half* __restrict__ Bt,
    const float* __restrict__ bias, const float* __restrict__ res,
    OutT* __restrict__ C) {
  extern __shared__ char smc[];
  const uint32_t sb = (uint32_t)__cvta_generic_to_shared(smc);
  const int tid = threadIdx.x;
  const int cRow = blockIdx.y, cCol = blockIdx.x;
  const int lane = tid & 31, warp = tid >> 5;
  const int lr = lane >> 2, lc = lane & 3;
  const int m0 = (warp & 1) * 64;
  const int n0 = (warp >> 1) * 32;

  const int row = tid >> 2;
  const int ch = tid & 3;

  const __half* Ap = A + (size_t)(cRow * 128 + row) * DMODEL + ch * 8;
  const __half* Bp = Bt + (size_t)(cCol * 128 + row) * DMODEL + ch * 8;

  float acc[4][4][4];
#pragma unroll
  for (int i = 0; i < 4; i++)
#pragma unroll
    for (int j = 0; j < 4; j++)
#pragma unroll
      for (int q = 0; q < 4; q++) acc[i][j][q] = 0.f;

  const int NT = DMODEL / HBK;

  auto issue = [&](int s, int t) {
    char* base = smc + s * HSTAGE_BYTES;
    const int k0 = t * HBK;
    cp_async16(base + row * HROWB + ch * 16, Ap + k0);
    cp_async16(base + (row + 64) * HROWB + ch * 16, Ap + (size_t)64 * DMODEL + k0);
    cp_async16(base + HA_BYTES + row * HROWB + ch * 16, Bp + k0);
    cp_async16(base + HA_BYTES + (row + 64) * HROWB + ch * 16,
               Bp + (size_t)64 * DMODEL + k0);
  };

#pragma unroll
  for (int s = 0; s < HNSTAGE - 1; s++) { issue(s, s); cp_commit(); }

  const uint32_t aoff = (m0 + (lane & 15)) * HROWB + (lane >> 4) * 16;
  const uint32_t boff =
      (n0 + (lane & 7) + ((lane >> 4) & 1) * 8) * HROWB + ((lane >> 3) & 1) * 16;

  for (int t = 0; t < NT; t++) {
    cp_wait<HNSTAGE - 2>();
    __syncthreads();

    const uint32_t sA = sb + (t & (HNSTAGE - 1)) * HSTAGE_BYTES;
    const uint32_t sB = sA + HA_BYTES;

#pragma unroll
    for (int ks = 0; ks < 2; ks++) {
      uint32_t af[4][4], bf[4][2];
#pragma unroll
      for (int mt = 0; mt < 4; mt++)
        ldsm_x4(af[mt][0], af[mt][1], af[mt][2], af[mt][3],
                sA + aoff + mt * 16 * HROWB + ks * 32);
#pragma unroll
      for (int ntp = 0; ntp < 2; ntp++) {
        uint32_t t0, t1, t2, t3;
        ldsm_x4(t0, t1, t2, t3, sB + boff + ntp * 16 * HROWB + ks * 32);
        bf[2 * ntp][0] = t0;     bf[2 * ntp][1] = t1;
        bf[2 * ntp + 1][0] = t2; bf[2 * ntp + 1][1] = t3;
      }
#pragma unroll
      for (int mt = 0; mt < 4; mt++)
#pragma unroll
        for (int nt = 0; nt < 4; nt++)
          mma_f16(acc[mt][nt][0], acc[mt][nt][1], acc[mt][nt][2], acc[mt][nt][3],
                  af[mt][0], af[mt][1], af[mt][2], af[mt][3],
                  bf[nt][0], bf[nt][1]);
    }

    if (t + HNSTAGE - 1 < NT)
      issue((t + HNSTAGE - 1) & (HNSTAGE - 1), t + HNSTAGE - 1);
    cp_commit();
  }

#pragma unroll
  for (int mt = 0; mt < 4; mt++) {
    const int r0 = cRow * 128 + m0 + mt * 16 + lr;
#pragma unroll
    for (int nt = 0; nt < 4; nt++) {
      const int col = cCol * 128 + n0 + nt * 8 + 2 * lc;
      const float bx = bias[col], by = bias[col + 1];
      float v0 = acc[mt][nt][0] + bx, v1 = acc[mt][nt][1] + by;
      float v2 = acc[mt][nt][2] + bx, v3 = acc[mt][nt][3] + by;
      if (EPI == 1) { v0 = gelu_f(v0); v1 = gelu_f(v1); v2 = gelu_f(v2); v3 = gelu_f(v3); }
      if (EPI == 2) {
        const float2 r4a = *(const float2*)(res + (size_t)r0 * DMODEL + col);
        const float2 r4b = *(const float2*)(res + (size_t)(r0 + 8) * DMODEL + col);
        v0 += r4a.x; v1 += r4a.y; v2 += r4b.x; v3 += r4b.y;
      }
      if (sizeof(OutT) == 2) {
        __half2 h0 = __floats2half2_rn(v0, v1);
        __half2 h1 = __floats2half2_rn(v2, v3);
        *(__half2*)((__half*)C + (size_t)r0 * DMODEL + col) = h0;
        *(__half2*)((__half*)C + (size_t)(r0 + 8) * DMODEL + col) = h1;
      } else {
        float2 o0 = {v0, v1}, o1 = {v2, v3};
        *(float2*)((float*)C + (size_t)r0 * DMODEL + col) = o0;
        *(float2*)((float*)C + (size_t)(r0 + 8) * DMODEL + col) = o1;
      }
    }
  }
}

template <int EPI, typename OutT>
__global__ void __launch_bounds__(256) hgemm_kernel(
    const __half* __restrict__ A, const __half* __restrict__ Bt,
    const float* __restrict__ bias, const float* __restrict__ res,
    OutT* __restrict__ C) {
  hgemm_body<EPI, OutT>(A, Bt, bias, res, C);
}

__global__ void __launch_bounds__(256) hqkv_kernel(
    const __half* __restrict__ A, const __half* __restrict__ wt,
    const float* __restrict__ bq, __half* __restrict__ q,
    const float* __restrict__ bk, __half* __restrict__ k,
    const float* __restrict__ bv, __half* __restrict__ v) {
  const __half* Bt;
  const float* bias;
  __half* C;
  if (blockIdx.z == 0)      { Bt = wt;                               bias = bq; C = q; }
  else if (blockIdx.z == 1) { Bt = wt + (size_t)DMODEL * DMODEL;     bias = bk; C = k; }
  else                      { Bt = wt + (size_t)2 * DMODEL * DMODEL; bias = bv; C = v; }
  hgemm_body<0, __half>(A, Bt, bias, nullptr, C);
}

// ---------------------------------------------------------------------------
// Flash attention (causal), fp16 mma, warp-local RAW-DOMAIN softmax.
// exp computed as exp2f(fma(s, C2, -m*C2)), C2 = 0.125*log2(e): no separate
// scale pass, one FFMA + one MUFU per score. Long CTAs scheduled first.
// ---------------------------------------------------------------------------
#define AT_STR 72
#define AT_QOFF 0
#define AT_KOFF 18432
#define AT_VOFF 36864
#define ATTN_SMEM_H (18432 * 3)   // 55296
#define SOFT_C2 0.18033688011112042f   // 0.125 * log2(e)

__global__ void __launch_bounds__(256, 2) flash_attn_h16_kernel(
    const __half* __restrict__ Q, const __half* __restrict__ K,
    const __half* __restrict__ V, __half* __restrict__ O) {
  extern __shared__ char smc[];
  const uint32_t sb = (uint32_t)__cvta_generic_to_shared(smc);
  __half* Qf = (__half*)(smc + AT_QOFF);
  __half* Kf = (__half*)(smc + AT_KOFF);
  __half* Vf = (__half*)(smc + AT_VOFF);

  // reversed mapping: longest-running tiles (largest bx) launch first
  const int bx = (SEQ / 128 - 1) - blockIdx.x;
  const int h = blockIdx.y, b = blockIdx.z;
  const int tid = threadIdx.x, lane = tid & 31, warp = tid >> 5;
  const int lr = lane >> 2, lc = lane & 3;
  const int mq = warp * 16;
  const int q0 = bx * 128;

#pragma unroll
  for (int i = 0; i < 4; i++) {
    const int idx = tid + i * 256;
    const int r = idx >> 3, c = idx & 7;
    cp_async16(Qf + r * AT_STR + c * 8,
               Q + (((size_t)((b * SEQ + q0 + r) * NHEAD + h)) << 6) + c * 8);
  }
#pragma unroll
  for (int i = 0; i < 2; i++) {
    const int idx = tid + i * 256;
    const int r = idx >> 3, c = idx & 7;
    const size_t g = (((size_t)((b * SEQ + r) * NHEAD + h)) << 6) + c * 8;
    cp_async16(Kf + r * AT_STR + c * 8, K + g);
    cp_async16(Vf + r * AT_STR + c * 8, V + g);
  }
  cp_commit();
  cp_wait<0>();
  __syncthreads();

  uint32_t qa[4][4];
  {
    const int qrow = mq + (lane & 15);
#pragma unroll
    for (int ks = 0; ks < 4; ks++) {
      const uint32_t a = sb + AT_QOFF +
                         (qrow * AT_STR + ks * 16 + (lane >> 4) * 8) * 2;
      ldsm_x4(qa[ks][0], qa[ks][1], qa[ks][2], qa[ks][3], a);
    }
  }

  float oacc[8][4];
#pragma unroll
  for (int nt = 0; nt < 8; nt++)
#pragma unroll
    for (int q = 0; q < 4; q++) oacc[nt][q] = 0.f;

  const int gr0 = q0 + mq + lr, gr1 = gr0 + 8;
  float mrow0 = -1e30f, mrow1 = -1e30f, lrow0 = 0.f, lrow1 = 0.f;

  const int ktmax = 2 * bx + 1;
  for (int kt = 0; kt <= ktmax; kt++) {
    const int buf = kt & 1;
    __syncthreads();
    if (kt < ktmax) {
      const int nb = buf ^ 1;
#pragma unroll
      for (int i = 0; i < 2; i++) {
        const int idx = tid + i * 256;
        const int r = idx >> 3, c = idx & 7;
        const size_t g =
            (((size_t)((b * SEQ + (kt + 1) * 64 + r) * NHEAD + h)) << 6) + c * 8;
        cp_async16(Kf + nb * 4608 + r * AT_STR + c * 8, K + g);
        cp_async16(Vf + nb * 4608 + r * AT_STR + c * 8, V + g);
      }
      cp_commit();
      cp_wait<1>();
    } else {
      cp_wait<0>();
    }
    __syncthreads();

    const uint32_t kbase = sb + AT_KOFF + buf * 9216;
    const uint32_t vbase = sb + AT_VOFF + buf * 9216;

    // ---- S = Q @ K^T (raw, unscaled) ----
    float sacc[8][4];
#pragma unroll
    for (int nt = 0; nt < 8; nt++)
#pragma unroll
      for (int q = 0; q < 4; q++) sacc[nt][q] = 0.f;
#pragma unroll
    for (int ks = 0; ks < 4; ks++) {
      uint32_t kb[8][2];
#pragma unroll
      for (int hh = 0; hh < 4; hh++) {
        const uint32_t a = kbase +
            ((hh * 16 + (lane & 15)) * AT_STR + ks * 16 + (lane >> 4) * 8) * 2;
        uint32_t t0, t1, t2, t3;
        ldsm_x4(t0, t1, t2, t3, a);
        kb[2 * hh][0] = t0; kb[2 * hh + 1][0] = t1;
        kb[2 * hh][1] = t2; kb[2 * hh + 1][1] = t3;
      }
#pragma unroll
      for (int nt = 0; nt < 8; nt++)
        mma_f16(sacc[nt][0], sacc[nt][1], sacc[nt][2], sacc[nt][3],
                qa[ks][0], qa[ks][1], qa[ks][2], qa[ks][3],
                kb[nt][0], kb[nt][1]);
    }

    // ---- causal mask (raw domain) ----
    if (kt >= 2 * bx) {
      const int kb0 = kt * 64;
#pragma unroll
      for (int nt = 0; nt < 8; nt++) {
        const int kcol = kb0 + nt * 8 + 2 * lc;
        if (kcol > gr0) sacc[nt][0] = -1e9f;
        if (kcol + 1 > gr0) sacc[nt][1] = -1e9f;
        if (kcol > gr1) sacc[nt][2] = -1e9f;
        if (kcol + 1 > gr1) sacc[nt][3] = -1e9f;
      }
    }

    // ---- warp-local online softmax in raw domain ----
    float tm0 = sacc[0][0], tm1 = sacc[0][2];
#pragma unroll
    for (int nt = 0; nt < 8; nt++) {
      tm0 = fmaxf(tm0, fmaxf(sacc[nt][0], sacc[nt][1]));
      tm1 = fmaxf(tm1, fmaxf(sacc[nt][2], sacc[nt][3]));
    }
    tm0 = fmaxf(tm0, __shfl_xor_sync(0xffffffffu, tm0, 1));
    tm0 = fmaxf(tm0, __shfl_xor_sync(0xffffffffu, tm0, 2));
    tm1 = fmaxf(tm1, __shfl_xor_sync(0xffffffffu, tm1, 1));
    tm1 = fmaxf(tm1, __shfl_xor_sync(0xffffffffu, tm1, 2));
    const float mnew0 = fmaxf(mrow0, tm0), mnew1 = fmaxf(mrow1, tm1);
    const float corr0 = exp2f((mrow0 - mnew0) * SOFT_C2);
    const float corr1 = exp2f((mrow1 - mnew1) * SOFT_C2);
    const float mc0 = mnew0 * SOFT_C2, mc1 = mnew1 * SOFT_C2;

    float ps0 = 0.f, ps1 = 0.f;
#pragma unroll
    for (int nt = 0; nt < 8; nt++) {
      sacc[nt][0] = exp2f(fmaf(sacc[nt][0], SOFT_C2, -mc0));
      sacc[nt][1] = exp2f(fmaf(sacc[nt][1], SOFT_C2, -mc0));
      sacc[nt][2] = exp2f(fmaf(sacc[nt][2], SOFT_C2, -mc1));
      sacc[nt][3] = exp2f(fmaf(sacc[nt][3], SOFT_C2, -mc1));
      ps0 += sacc[nt][0] + sacc[nt][1];
      ps1 += sacc[nt][2] + sacc[nt][3];
    }
    ps0 += __shfl_xor_sync(0xffffffffu, ps0, 1);
    ps0 += __shfl_xor_sync(0xffffffffu, ps0, 2);
    ps1 += __shfl_xor_sync(0xffffffffu, ps1, 1);
    ps1 += __shfl_xor_sync(0xffffffffu, ps1, 2);
    lrow0 = lrow0 * corr0 + ps0;
    lrow1 = lrow1 * corr1 + ps1;
    mrow0 = mnew0; mrow1 = mnew1;

    uint32_t pa[4][4];
#pragma unroll
    for (int ks2 = 0; ks2 < 4; ks2++) {
      pa[ks2][0] = h2u(__floats2half2_rn(sacc[2 * ks2][0], sacc[2 * ks2][1]));
      pa[ks2][1] = h2u(__floats2half2_rn(sacc[2 * ks2][2], sacc[2 * ks2][3]));
      pa[ks2][2] = h2u(__floats2half2_rn(sacc[2 * ks2 + 1][0], sacc[2 * ks2 + 1][1]));
      pa[ks2][3] = h2u(__floats2half2_rn(sacc[2 * ks2 + 1][2], sacc[2 * ks2 + 1][3]));
    }

#pragma unroll
    for (int nt = 0; nt < 8; nt++) {
      oacc[nt][0] *= corr0; oacc[nt][1] *= corr0;
      oacc[nt][2] *= corr1; oacc[nt][3] *= corr1;
    }
#pragma unroll
    for (int ks2 = 0; ks2 < 4; ks2++) {
      uint32_t vb[8][2];
#pragma unroll
      for (int hh = 0; hh < 4; hh++) {
        const uint32_t a = vbase +
            ((ks2 * 16 + (lane & 15)) * AT_STR + hh * 16 + (lane >> 4) * 8) * 2;
        uint32_t t0, t1, t2, t3;
        ldsm_x4_t(t0, t1, t2, t3, a);
        vb[2 * hh][0] = t0;     vb[2 * hh][1] = t1;
        vb[2 * hh + 1][0] = t2; vb[2 * hh + 1][1] = t3;
      }
#pragma unroll
      for (int nt = 0; nt < 8; nt++)
        mma_f16(oacc[nt][0], oacc[nt][1], oacc[nt][2], oacc[nt][3],
                pa[ks2][0], pa[ks2][1], pa[ks2][2], pa[ks2][3],
                vb[nt][0], vb[nt][1]);
    }
  }

  const float inv0 = 1.0f / lrow0, inv1 = 1.0f / lrow1;
#pragma unroll
  for (int nt = 0; nt < 8; nt++) {
    const int col = nt * 8 + 2 * lc;
    __half* o0 = O + (((size_t)((b * SEQ + gr0) * NHEAD + h)) << 6) + col;
    __half* o1 = O + (((size_t)((b * SEQ + gr1) * NHEAD + h)) << 6) + col;
    *(__half2*)o0 = __floats2half2_rn(oacc[nt][0] * inv0, oacc[nt][1] * inv0);
    *(__half2*)o1 = __floats2half2_rn(oacc[nt][2] * inv1, oacc[nt][3] * inv1);
  }
}

// ---------------------------------------------------------------------------
// Launch
// ---------------------------------------------------------------------------
extern "C" void kernel_launch(void* const* d_in, const int* in_sizes, int n_in,
                              void* d_out, int out_size) {
  (void)in_sizes; (void)n_in; (void)out_size;
  const float* x      = (const float*)d_in[0];
  const float* Wq     = (const float*)d_in[2];
  const float* bq     = (const float*)d_in[3];
  const float* Wk     = (const float*)d_in[4];
  const float* bk     = (const float*)d_in[5];
  const float* Wv     = (const float*)d_in[6];
  const float* bv     = (const float*)d_in[7];
  const float* Wo     = (const float*)d_in[8];
  const float* bo     = (const float*)d_in[9];
  const float* W1     = (const float*)d_in[10];
  const float* b1     = (const float*)d_in[11];
  const float* W2     = (const float*)d_in[12];
  const float* b2     = (const float*)d_in[13];
  const float* alpha1 = (const float*)d_in[14];
  const float* bias1  = (const float*)d_in[15];
  const float* alpha2 = (const float*)d_in[16];
  const float* bias2  = (const float*)d_in[17];
  float* out = (float*)d_out;

  __half *x2h, *qh, *kh, *vh, *attnh, *ffh, *wth;
  float* xmid;
  cudaGetSymbolAddress((void**)&x2h, g_x2h);
  cudaGetSymbolAddress((void**)&qh, g_qh);
  cudaGetSymbolAddress((void**)&kh, g_kh);
  cudaGetSymbolAddress((void**)&vh, g_vh);
  cudaGetSymbolAddress((void**)&attnh, g_attnh);
  cudaGetSymbolAddress((void**)&ffh, g_ffh);
  cudaGetSymbolAddress((void**)&xmid, g_xmid);
  cudaGetSymbolAddress((void**)&wth, g_wth);

  cudaFuncSetAttribute(flash_attn_h16_kernel,
                       cudaFuncAttributeMaxDynamicSharedMemorySize, ATTN_SMEM_H);
  cudaFuncSetAttribute(hgemm_kernel<1, __half>,
                       cudaFuncAttributeMaxDynamicSharedMemorySize, HGEMM_SMEM);
  cudaFuncSetAttribute(hgemm_kernel<2, float>,
                       cudaFuncAttributeMaxDynamicSharedMemorySize, HGEMM_SMEM);
  cudaFuncSetAttribute(hqkv_kernel,
                       cudaFuncAttributeMaxDynamicSharedMemorySize, HGEMM_SMEM);

  const dim3 gemm_grid(DMODEL / 128, ROWS / 128);
  const dim3 qkv_grid(DMODEL / 128, ROWS / 128, 3);

  transpose6_kernel<<<dim3(32, 32, 6), dim3(32, 8)>>>(Wq, Wk, Wv, Wo, W1, W2, wth);
  layernorm_kernel<<<ROWS, 256>>>(x, alpha1, bias1, x2h);
  hqkv_kernel<<<qkv_grid, 256, HGEMM_SMEM>>>(x2h, wth, bq, qh, bk, kh, bv, vh);
  flash_attn_h16_kernel<<<dim3(SEQ / 128, NHEAD, BATCH), 256, ATTN_SMEM_H>>>(
      qh, kh, vh, attnh);
  hgemm_kernel<2, float><<<gemm_grid, 256, HGEMM_SMEM>>>(
      attnh, wth + (size_t)3 * DMODEL * DMODEL, bo, x, xmid);
  layernorm_kernel<<<ROWS, 256>>>(xmid, alpha2, bias2, x2h);
  hgemm_kernel<1, __half><<<gemm_grid, 256, HGEMM_SMEM>>>(
      x2h, wth + (size_t)4 * DMODEL * DMODEL, b1, nullptr, ffh);
  hgemm_kernel<2, float><<<gemm_grid, 256, HGEMM_SMEM>>>(
      ffh, wth + (size_t)5 * DMODEL * DMODEL, b2, xmid, out);
}